// round 3
// baseline (speedup 1.0000x reference)
#include <cuda_runtime.h>
#include <math.h>

#define N_ 8
#define L_ 1024
#define H_ 16
#define D_ 64
#define E_ 1024
#define PW 68    // row-major smem pitch (floats)
#define PP 20    // permuted-layout pitch (floats per 16-value fragment row)
#define QT 128   // attention q-tile rows
#define KT 64    // attention k-tile rows

// Scratch (static device globals: allocation-free per harness rules)
__device__ float g_q[N_*H_*L_*D_];
__device__ float g_k[N_*H_*L_*D_];
__device__ float g_v[N_*H_*L_*D_];
__device__ float g_attn[N_*L_*H_*D_];

// ---------------------------------------------------------------------------
// tf32 helpers
// ---------------------------------------------------------------------------
__device__ __forceinline__ unsigned f2tf(float f) {
    unsigned u;
    asm("cvt.rna.tf32.f32 %0, %1;" : "=r"(u) : "f"(f));
    return u;
}
__device__ __forceinline__ float f2tff(float f) { return __uint_as_float(f2tf(f)); }

__device__ __forceinline__ void mma_tf32(float c[4],
                                         unsigned a0, unsigned a1, unsigned a2, unsigned a3,
                                         unsigned b0, unsigned b1) {
    asm volatile(
        "mma.sync.aligned.m16n8k8.row.col.f32.tf32.tf32.f32 "
        "{%0,%1,%2,%3}, {%4,%5,%6,%7}, {%8,%9}, {%0,%1,%2,%3};"
        : "+f"(c[0]), "+f"(c[1]), "+f"(c[2]), "+f"(c[3])
        : "r"(a0), "r"(a1), "r"(a2), "r"(a3), "r"(b0), "r"(b1));
}
#define U(x) __float_as_uint(x)

// ---------------------------------------------------------------------------
// Kernel 1: QKV projection (fp32 exact; vectorized LDS.128 both operands)
// Output cols per thread: c0 + 16*c with c0 = tx  (conflict-free W loads)
// ---------------------------------------------------------------------------
__global__ void __launch_bounds__(256, 1)
sa_qkv_kernel(const float* __restrict__ x,
              const float* __restrict__ Wq, const float* __restrict__ bq,
              const float* __restrict__ Wk, const float* __restrict__ bk,
              const float* __restrict__ Wv, const float* __restrict__ bv)
{
    __shared__ float zs[64 * PW];
    __shared__ float ws[64 * PW];

    const int t  = threadIdx.x;
    const int tx = t & 15, ty = t >> 4;
    const int r0 = ty * 4;
    const int c0 = tx;
    const int R0 = blockIdx.x * 64;

    for (int i = t; i < 64 * 16; i += 256) {
        int row = i >> 4, cg = i & 15;
        float4 v4 = *(const float4*)&x[(size_t)(R0 + row) * D_ + cg * 4];
        *(float4*)&zs[row * PW + cg * 4] = v4;
    }

    size_t obase[4];
    #pragma unroll
    for (int r = 0; r < 4; r++) {
        int R = R0 + r0 + r;
        int n = R / (L_ * H_);
        int rem = R % (L_ * H_);
        int l = rem / H_;
        int h = rem % H_;
        obase[r] = ((size_t)((n * H_ + h) * L_ + l)) * D_;
    }

    const float* Ws[3] = {Wq, Wk, Wv};
    const float* Bs[3] = {bq, bk, bv};
    float*       Gs[3] = {g_q, g_k, g_v};

    #pragma unroll
    for (int m = 0; m < 3; m++) {
        __syncthreads();
        for (int i = t; i < 64 * 16; i += 256) {
            int row = i >> 4, cg = i & 15;
            float4 v4 = *(const float4*)&Ws[m][row * D_ + cg * 4];
            *(float4*)&ws[row * PW + cg * 4] = v4;
        }
        __syncthreads();

        float acc[4][4] = {};
        #pragma unroll
        for (int d4 = 0; d4 < 16; d4++) {
            float4 zf[4], wf[4];
            #pragma unroll
            for (int r = 0; r < 4; r++) zf[r] = *(const float4*)&zs[(r0 + r) * PW + d4 * 4];
            #pragma unroll
            for (int c = 0; c < 4; c++) wf[c] = *(const float4*)&ws[(c0 + 16 * c) * PW + d4 * 4];
            #pragma unroll
            for (int r = 0; r < 4; r++)
                #pragma unroll
                for (int c = 0; c < 4; c++)
                    acc[r][c] += zf[r].x * wf[c].x + zf[r].y * wf[c].y
                               + zf[r].z * wf[c].z + zf[r].w * wf[c].w;
        }

        #pragma unroll
        for (int r = 0; r < 4; r++)
            #pragma unroll
            for (int c = 0; c < 4; c++)
                Gs[m][obase[r] + c0 + 16 * c] = acc[r][c] + Bs[m][c0 + 16 * c];
    }
}

// ---------------------------------------------------------------------------
// Kernel 2: fused attention, tf32 mma.sync.
// K and Erel band staged in fragment-permuted layout:
//   perm[(row*4 + d%4)*PP + d/4]  -> one float4 = b0,b1 for two k-steps,
//   lane stride 80B -> conflict-free LDS.128 and staging STS.
// ---------------------------------------------------------------------------
__global__ void __launch_bounds__(256, 1)
sa_attn_mma(const float* __restrict__ Erel)
{
    extern __shared__ float sm[];
    float* kp_s = sm;                     // 256 x PP  (perm K)
    float* v_s  = kp_s + 256 * PP;        // KT x PW
    float* p_s  = v_s  + KT * PW;         // QT x PW  (softmax weights)
    float* b_s  = p_s  + QT * PW;         // QT x PW  (bias weights)
    float* ep_s = b_s  + QT * PW;         // 768 x PP (perm Erel band)
    float* q_s  = ep_s;                   // alias: Q staging before main loop

    const int qt8 = blockIdx.x;
    const int h   = blockIdx.y;
    const int n   = blockIdx.z;
    const int q0  = qt8 * QT;

    const size_t hb = ((size_t)(n * H_ + h)) * L_ * D_;
    const float* qp = g_q + hb;
    const float* kp = g_k + hb;
    const float* vp = g_v + hb;

    const int t    = threadIdx.x;
    const int lane = t & 31;
    const int w    = t >> 5;
    const int grp  = lane >> 2;    // 0..7
    const int qd   = lane & 3;     // 0..3
    const int wr0  = w * 16;       // warp's first local q row

    // ---- stage Q tile, build per-warp tf32 A fragments (held all kernel)
    for (int i = t; i < QT * 16; i += 256) {
        int row = i >> 4, cg = i & 15;
        float4 v4 = *(const float4*)&qp[(size_t)(q0 + row) * D_ + cg * 4];
        *(float4*)&q_s[row * PW + cg * 4] = v4;
    }
    __syncthreads();

    unsigned qa[8][4];
    {
        int rA = wr0 + grp, rB = rA + 8;
        #pragma unroll
        for (int ks = 0; ks < 8; ks++) {
            qa[ks][0] = f2tf(q_s[rA * PW + ks * 8 + qd]);
            qa[ks][1] = f2tf(q_s[rB * PW + ks * 8 + qd]);
            qa[ks][2] = f2tf(q_s[rA * PW + ks * 8 + qd + 4]);
            qa[ks][3] = f2tf(q_s[rB * PW + ks * 8 + qd + 4]);
        }
    }

    float accS[8][4] = {};
    float accB[8][4] = {};
    float m_lo = -INFINITY, m_hi = -INFINITY;
    float l_lo = 0.f, l_hi = 0.f;
    const float scale = 0.03125f;   // 1/sqrt(1024)

    const unsigned* vu = (const unsigned*)v_s;
    const unsigned* pu = (const unsigned*)p_s;
    const unsigned* bu = (const unsigned*)b_s;

    for (int kt = 0; kt < 16; kt++) {
        const int  k0   = kt * KT;
        const bool hasb = (k0 <= q0 + QT - 1);

        __syncthreads();   // consumers of kp_s/v_s/ep_s done (also guards q_s alias)
        for (int i = t; i < KT * 16; i += 256) {
            int row = i >> 4, cg = i & 15;
            float4 kv = *(const float4*)&kp[(size_t)(k0 + row) * D_ + cg * 4];
            float4 vv = *(const float4*)&vp[(size_t)(k0 + row) * D_ + cg * 4];
            // K -> permuted tf32
            kp_s[(row * 4 + 0) * PP + cg] = f2tff(kv.x);
            kp_s[(row * 4 + 1) * PP + cg] = f2tff(kv.y);
            kp_s[(row * 4 + 2) * PP + cg] = f2tff(kv.z);
            kp_s[(row * 4 + 3) * PP + cg] = f2tff(kv.w);
            // V -> row-major tf32
            v_s[row * PW + cg * 4 + 0] = f2tff(vv.x);
            v_s[row * PW + cg * 4 + 1] = f2tff(vv.y);
            v_s[row * PW + cg * 4 + 2] = f2tff(vv.z);
            v_s[row * PW + cg * 4 + 3] = f2tff(vv.w);
        }
        if (hasb) {
            const int rb = L_ - QT - q0 + k0;   // >= 0 always
            for (int i = t; i < 192 * 16; i += 256) {
                int row = i >> 4, cg = i & 15;
                int rr = rb + row;
                float4 e4 = (rr < L_) ? *(const float4*)&Erel[(size_t)rr * D_ + cg * 4]
                                      : make_float4(0.f, 0.f, 0.f, 0.f);
                ep_s[(row * 4 + 0) * PP + cg] = f2tff(e4.x);
                ep_s[(row * 4 + 1) * PP + cg] = f2tff(e4.y);
                ep_s[(row * 4 + 2) * PP + cg] = f2tff(e4.z);
                ep_s[(row * 4 + 3) * PP + cg] = f2tff(e4.w);
            }
        }
        __syncthreads();

        // ---- S = Q K^T (per warp: 16 x 64), vectorized b-frag loads ----
        float sfr[8][4];
        #pragma unroll
        for (int nt = 0; nt < 8; nt++) {
            sfr[nt][0] = sfr[nt][1] = sfr[nt][2] = sfr[nt][3] = 0.f;
            const float4* kb4 = (const float4*)&kp_s[((nt * 8 + grp) * 4 + qd) * PP];
            #pragma unroll
            for (int m = 0; m < 4; m++) {
                float4 f = kb4[m];
                mma_tf32(sfr[nt], qa[2*m][0],   qa[2*m][1],   qa[2*m][2],   qa[2*m][3],   U(f.x), U(f.y));
                mma_tf32(sfr[nt], qa[2*m+1][0], qa[2*m+1][1], qa[2*m+1][2], qa[2*m+1][3], U(f.z), U(f.w));
            }
        }

        // ---- online softmax (rows lane>>2 and +8) ----
        float mt_lo = -INFINITY, mt_hi = -INFINITY;
        #pragma unroll
        for (int nt = 0; nt < 8; nt++) {
            #pragma unroll
            for (int r = 0; r < 4; r++) sfr[nt][r] *= scale;
            mt_lo = fmaxf(mt_lo, fmaxf(sfr[nt][0], sfr[nt][1]));
            mt_hi = fmaxf(mt_hi, fmaxf(sfr[nt][2], sfr[nt][3]));
        }
        mt_lo = fmaxf(mt_lo, __shfl_xor_sync(0xffffffffu, mt_lo, 1));
        mt_lo = fmaxf(mt_lo, __shfl_xor_sync(0xffffffffu, mt_lo, 2));
        mt_hi = fmaxf(mt_hi, __shfl_xor_sync(0xffffffffu, mt_hi, 1));
        mt_hi = fmaxf(mt_hi, __shfl_xor_sync(0xffffffffu, mt_hi, 2));

        float mn_lo = fmaxf(m_lo, mt_lo);
        float mn_hi = fmaxf(m_hi, mt_hi);
        float f_lo  = __expf(m_lo - mn_lo);
        float f_hi  = __expf(m_hi - mn_hi);
        m_lo = mn_lo; m_hi = mn_hi;

        float rs_lo = 0.f, rs_hi = 0.f;
        {
            int rA = wr0 + grp, rB = rA + 8;
            #pragma unroll
            for (int nt = 0; nt < 8; nt++) {
                float p0 = __expf(sfr[nt][0] - mn_lo);
                float p1 = __expf(sfr[nt][1] - mn_lo);
                float p2 = __expf(sfr[nt][2] - mn_hi);
                float p3 = __expf(sfr[nt][3] - mn_hi);
                rs_lo += p0 + p1;
                rs_hi += p2 + p3;
                float2 plo = make_float2(f2tff(p0), f2tff(p1));
                float2 phi = make_float2(f2tff(p2), f2tff(p3));
                *(float2*)&p_s[rA * PW + nt * 8 + 2 * qd] = plo;
                *(float2*)&p_s[rB * PW + nt * 8 + 2 * qd] = phi;
            }
        }
        rs_lo += __shfl_xor_sync(0xffffffffu, rs_lo, 1);
        rs_lo += __shfl_xor_sync(0xffffffffu, rs_lo, 2);
        rs_hi += __shfl_xor_sync(0xffffffffu, rs_hi, 1);
        rs_hi += __shfl_xor_sync(0xffffffffu, rs_hi, 2);
        l_lo = l_lo * f_lo + rs_lo;
        l_hi = l_hi * f_hi + rs_hi;
        #pragma unroll
        for (int nt = 0; nt < 8; nt++) {
            accS[nt][0] *= f_lo; accS[nt][1] *= f_lo;
            accS[nt][2] *= f_hi; accS[nt][3] *= f_hi;
        }

        // ---- bias scores: G = Q Eband^T, scatter diagonal j = c - 127 + r.
        //      Per-thread windows cover every (r, j in [0,64)) cell exactly once,
        //      so write (valid ? g : 0) with no pre-zero pass. ----
        if (hasb) {
            const int nt_lo = (112 - wr0) >> 3;
            int rA = wr0 + grp, rB = rA + 8;
            #pragma unroll
            for (int nn = 0; nn < 10; nn++) {
                int nt = nt_lo + nn;
                float g[4] = {0.f, 0.f, 0.f, 0.f};
                const float4* eb4 = (const float4*)&ep_s[((nt * 8 + grp) * 4 + qd) * PP];
                #pragma unroll
                for (int m = 0; m < 4; m++) {
                    float4 f = eb4[m];
                    mma_tf32(g, qa[2*m][0],   qa[2*m][1],   qa[2*m][2],   qa[2*m][3],   U(f.x), U(f.y));
                    mma_tf32(g, qa[2*m+1][0], qa[2*m+1][1], qa[2*m+1][2], qa[2*m+1][3], U(f.z), U(f.w));
                }
                int cc = nt * 8 + 2 * qd;
                #pragma unroll
                for (int e = 0; e < 4; e++) {
                    int r = (e >= 2) ? rB : rA;
                    int c = cc + (e & 1);
                    int j = c - (QT - 1) + r;
                    if (j >= 0 && j < KT) {
                        bool ok = (k0 + j) <= (q0 + r);
                        b_s[r * PW + j] = ok ? f2tff(g[e]) : 0.f;
                    }
                }
            }
        }
        __syncwarp();   // p_s/b_s rows are warp-private; order STS -> LDS within warp

        // ---- accumulate P @ V (and B @ V) ----
        if (hasb) {
            int rA = wr0 + grp, rB = rA + 8;
            #pragma unroll
            for (int ks = 0; ks < 8; ks++) {
                unsigned pa0 = pu[rA * PW + ks * 8 + qd];
                unsigned pa1 = pu[rB * PW + ks * 8 + qd];
                unsigned pa2 = pu[rA * PW + ks * 8 + qd + 4];
                unsigned pa3 = pu[rB * PW + ks * 8 + qd + 4];
                unsigned ba0 = bu[rA * PW + ks * 8 + qd];
                unsigned ba1 = bu[rB * PW + ks * 8 + qd];
                unsigned ba2 = bu[rA * PW + ks * 8 + qd + 4];
                unsigned ba3 = bu[rB * PW + ks * 8 + qd + 4];
                #pragma unroll
                for (int nt = 0; nt < 8; nt++) {
                    unsigned vb0 = vu[(ks * 8 + qd) * PW + nt * 8 + grp];
                    unsigned vb1 = vu[(ks * 8 + qd + 4) * PW + nt * 8 + grp];
                    mma_tf32(accS[nt], pa0, pa1, pa2, pa3, vb0, vb1);
                    mma_tf32(accB[nt], ba0, ba1, ba2, ba3, vb0, vb1);
                }
            }
        } else {
            int rA = wr0 + grp, rB = rA + 8;
            #pragma unroll
            for (int ks = 0; ks < 8; ks++) {
                unsigned pa0 = pu[rA * PW + ks * 8 + qd];
                unsigned pa1 = pu[rB * PW + ks * 8 + qd];
                unsigned pa2 = pu[rA * PW + ks * 8 + qd + 4];
                unsigned pa3 = pu[rB * PW + ks * 8 + qd + 4];
                #pragma unroll
                for (int nt = 0; nt < 8; nt++) {
                    unsigned vb0 = vu[(ks * 8 + qd) * PW + nt * 8 + grp];
                    unsigned vb1 = vu[(ks * 8 + qd + 4) * PW + nt * 8 + grp];
                    mma_tf32(accS[nt], pa0, pa1, pa2, pa3, vb0, vb1);
                }
            }
        }
    }

    // ---- epilogue: out[n, q, h, d] = accS/l + accB ----
    {
        float inv_lo = 1.f / l_lo;
        float inv_hi = 1.f / l_hi;
        int iA = q0 + wr0 + grp;
        int iB = iA + 8;
        float* opA = g_attn + ((size_t)((n * L_ + iA) * H_ + h)) * D_;
        float* opB = g_attn + ((size_t)((n * L_ + iB) * H_ + h)) * D_;
        #pragma unroll
        for (int nt = 0; nt < 8; nt++) {
            int d = nt * 8 + 2 * qd;
            float2 olo = make_float2(accS[nt][0] * inv_lo + accB[nt][0],
                                     accS[nt][1] * inv_lo + accB[nt][1]);
            float2 ohi = make_float2(accS[nt][2] * inv_hi + accB[nt][2],
                                     accS[nt][3] * inv_hi + accB[nt][3]);
            *(float2*)&opA[d] = olo;
            *(float2*)&opB[d] = ohi;
        }
    }
}

// ---------------------------------------------------------------------------
// Kernel 3: output projection, tf32 mma.sync, permuted-layout LDS.128 frags.
// out(8192,1024) = g_attn(8192,1024) @ Wo^T + bo
// CTA tile 128x128, k-chunks of 64; warp tile 64x32.
// ---------------------------------------------------------------------------
__global__ void __launch_bounds__(256, 1)
sa_outproj_mma(const float* __restrict__ Wo, const float* __restrict__ bo,
               float* __restrict__ out)
{
    extern __shared__ float sm[];
    float* ap_s = sm;                // 512 x PP (perm A)
    float* wp_s = sm + 512 * PP;     // 512 x PP (perm W)

    const int e0 = blockIdx.x * 128;
    const int m0 = blockIdx.y * 128;
    const int t    = threadIdx.x;
    const int lane = t & 31;
    const int w    = t >> 5;
    const int grp  = lane >> 2;
    const int qd   = lane & 3;
    const int wm   = (w >> 2) * 64;   // warp m offset (0 or 64)
    const int wn   = (w & 3) * 32;    // warp n offset (0,32,64,96)

    float acc[4][4][4] = {};

    for (int kc = 0; kc < E_; kc += 64) {
        __syncthreads();
        for (int i = t; i < 128 * 16; i += 256) {
            int row = i >> 4, cg = i & 15;
            float4 a4 = *(const float4*)&g_attn[(size_t)(m0 + row) * E_ + kc + cg * 4];
            float4 w4 = *(const float4*)&Wo[(size_t)(e0 + row) * E_ + kc + cg * 4];
            ap_s[(row * 4 + 0) * PP + cg] = f2tff(a4.x);
            ap_s[(row * 4 + 1) * PP + cg] = f2tff(a4.y);
            ap_s[(row * 4 + 2) * PP + cg] = f2tff(a4.z);
            ap_s[(row * 4 + 3) * PP + cg] = f2tff(a4.w);
            wp_s[(row * 4 + 0) * PP + cg] = f2tff(w4.x);
            wp_s[(row * 4 + 1) * PP + cg] = f2tff(w4.y);
            wp_s[(row * 4 + 2) * PP + cg] = f2tff(w4.z);
            wp_s[(row * 4 + 3) * PP + cg] = f2tff(w4.w);
        }
        __syncthreads();

        // B-frags for all 4 n-tiles (16 LDS.128)
        float4 wf[4][4];
        #pragma unroll
        for (int nt = 0; nt < 4; nt++) {
            const float4* wb4 = (const float4*)&wp_s[((wn + nt * 8 + grp) * 4 + qd) * PP];
            #pragma unroll
            for (int m = 0; m < 4; m++) wf[nt][m] = wb4[m];
        }

        #pragma unroll
        for (int mt = 0; mt < 4; mt++) {
            int rA = wm + mt * 16 + grp;
            const float4* aA4 = (const float4*)&ap_s[(rA * 4 + qd) * PP];
            const float4* aB4 = (const float4*)&ap_s[((rA + 8) * 4 + qd) * PP];
            float4 fA[4], fB[4];
            #pragma unroll
            for (int m = 0; m < 4; m++) { fA[m] = aA4[m]; fB[m] = aB4[m]; }
            #pragma unroll
            for (int m = 0; m < 4; m++) {
                #pragma unroll
                for (int nt = 0; nt < 4; nt++) {
                    mma_tf32(acc[mt][nt], U(fA[m].x), U(fB[m].x), U(fA[m].y), U(fB[m].y),
                             U(wf[nt][m].x), U(wf[nt][m].y));
                    mma_tf32(acc[mt][nt], U(fA[m].z), U(fB[m].z), U(fA[m].w), U(fB[m].w),
                             U(wf[nt][m].z), U(wf[nt][m].w));
                }
            }
        }
    }

    // epilogue
    #pragma unroll
    for (int mt = 0; mt < 4; mt++) {
        int rA = m0 + wm + mt * 16 + grp;
        int rB = rA + 8;
        #pragma unroll
        for (int nt = 0; nt < 4; nt++) {
            int col = e0 + wn + nt * 8 + 2 * qd;
            float b0 = bo[col], b1 = bo[col + 1];
            float2 olo = make_float2(acc[mt][nt][0] + b0, acc[mt][nt][1] + b1);
            float2 ohi = make_float2(acc[mt][nt][2] + b0, acc[mt][nt][3] + b1);
            *(float2*)&out[(size_t)rA * E_ + col] = olo;
            *(float2*)&out[(size_t)rB * E_ + col] = ohi;
        }
    }
}

// ---------------------------------------------------------------------------
extern "C" void kernel_launch(void* const* d_in, const int* in_sizes, int n_in,
                              void* d_out, int out_size)
{
    const float* x    = (const float*)d_in[0];
    const float* Wq   = (const float*)d_in[1];
    const float* bq   = (const float*)d_in[2];
    const float* Wk   = (const float*)d_in[3];
    const float* bk   = (const float*)d_in[4];
    const float* Wv   = (const float*)d_in[5];
    const float* bv   = (const float*)d_in[6];
    const float* Erel = (const float*)d_in[7];
    const float* Wo   = (const float*)d_in[8];
    const float* bo   = (const float*)d_in[9];
    float* out = (float*)d_out;

    // attn: kperm(256xPP) + v(64xPW) + p(128xPW) + b(128xPW) + eperm(768xPP)
    const int attn_smem = (256 * PP + 64 * PW + 128 * PW * 2 + 768 * PP) * (int)sizeof(float); // 168,960 B
    const int proj_smem = 2 * 512 * PP * (int)sizeof(float);                                   // 81,920 B
    cudaFuncSetAttribute(sa_attn_mma,
                         cudaFuncAttributeMaxDynamicSharedMemorySize, attn_smem);
    cudaFuncSetAttribute(sa_outproj_mma,
                         cudaFuncAttributeMaxDynamicSharedMemorySize, proj_smem);

    sa_qkv_kernel<<<(N_ * L_ * H_) / 64, 256>>>(x, Wq, bq, Wk, bk, Wv, bv);
    sa_attn_mma<<<dim3(L_ / QT, H_, N_), 256, attn_smem>>>(Erel);
    sa_outproj_mma<<<dim3(E_ / 128, (N_ * L_) / 128), 256, proj_smem>>>(Wo, bo, out);
}

// round 4
// speedup vs baseline: 1.2451x; 1.2451x over previous
#include <cuda_runtime.h>
#include <math.h>

#define N_ 8
#define L_ 1024
#define H_ 16
#define D_ 64
#define E_ 1024
#define PW 68    // smem pitch (floats)
#define QT 128   // attention q-tile rows
#define KT 64    // attention k-tile rows

// Scratch (static device globals: allocation-free per harness rules)
__device__ float g_q[N_*H_*L_*D_];
__device__ float g_k[N_*H_*L_*D_];
__device__ float g_v[N_*H_*L_*D_];
__device__ float g_attn[N_*L_*H_*D_];

// ---------------------------------------------------------------------------
// tf32 helpers
// ---------------------------------------------------------------------------
__device__ __forceinline__ unsigned f2tf(float f) {
    unsigned u;
    asm("cvt.rna.tf32.f32 %0, %1;" : "=r"(u) : "f"(f));
    return u;
}
__device__ __forceinline__ float f2tff(float f) { return __uint_as_float(f2tf(f)); }

__device__ __forceinline__ void mma_tf32(float c[4],
                                         unsigned a0, unsigned a1, unsigned a2, unsigned a3,
                                         unsigned b0, unsigned b1) {
    asm volatile(
        "mma.sync.aligned.m16n8k8.row.col.f32.tf32.tf32.f32 "
        "{%0,%1,%2,%3}, {%4,%5,%6,%7}, {%8,%9}, {%0,%1,%2,%3};"
        : "+f"(c[0]), "+f"(c[1]), "+f"(c[2]), "+f"(c[3])
        : "r"(a0), "r"(a1), "r"(a2), "r"(a3), "r"(b0), "r"(b1));
}

// ---------------------------------------------------------------------------
// Kernel 1: QKV projection (fp32 exact; vectorized LDS.128 both operands)
// ---------------------------------------------------------------------------
__global__ void __launch_bounds__(256, 1)
sa_qkv_kernel(const float* __restrict__ x,
              const float* __restrict__ Wq, const float* __restrict__ bq,
              const float* __restrict__ Wk, const float* __restrict__ bk,
              const float* __restrict__ Wv, const float* __restrict__ bv)
{
    __shared__ float zs[64 * PW];
    __shared__ float ws[64 * PW];

    const int t  = threadIdx.x;
    const int tx = t & 15, ty = t >> 4;
    const int r0 = ty * 4;
    const int c0 = tx;
    const int R0 = blockIdx.x * 64;

    for (int i = t; i < 64 * 16; i += 256) {
        int row = i >> 4, cg = i & 15;
        float4 v4 = *(const float4*)&x[(size_t)(R0 + row) * D_ + cg * 4];
        *(float4*)&zs[row * PW + cg * 4] = v4;
    }

    size_t obase[4];
    #pragma unroll
    for (int r = 0; r < 4; r++) {
        int R = R0 + r0 + r;
        int n = R / (L_ * H_);
        int rem = R % (L_ * H_);
        int l = rem / H_;
        int h = rem % H_;
        obase[r] = ((size_t)((n * H_ + h) * L_ + l)) * D_;
    }

    const float* Ws[3] = {Wq, Wk, Wv};
    const float* Bs[3] = {bq, bk, bv};
    float*       Gs[3] = {g_q, g_k, g_v};

    #pragma unroll
    for (int m = 0; m < 3; m++) {
        __syncthreads();
        for (int i = t; i < 64 * 16; i += 256) {
            int row = i >> 4, cg = i & 15;
            float4 v4 = *(const float4*)&Ws[m][row * D_ + cg * 4];
            *(float4*)&ws[row * PW + cg * 4] = v4;
        }
        __syncthreads();

        float acc[4][4] = {};
        #pragma unroll
        for (int d4 = 0; d4 < 16; d4++) {
            float4 zf[4], wf[4];
            #pragma unroll
            for (int r = 0; r < 4; r++) zf[r] = *(const float4*)&zs[(r0 + r) * PW + d4 * 4];
            #pragma unroll
            for (int c = 0; c < 4; c++) wf[c] = *(const float4*)&ws[(c0 + 16 * c) * PW + d4 * 4];
            #pragma unroll
            for (int r = 0; r < 4; r++)
                #pragma unroll
                for (int c = 0; c < 4; c++)
                    acc[r][c] += zf[r].x * wf[c].x + zf[r].y * wf[c].y
                               + zf[r].z * wf[c].z + zf[r].w * wf[c].w;
        }

        #pragma unroll
        for (int r = 0; r < 4; r++)
            #pragma unroll
            for (int c = 0; c < 4; c++)
                Gs[m][obase[r] + c0 + 16 * c] = acc[r][c] + Bs[m][c0 + 16 * c];
    }
}

// ---------------------------------------------------------------------------
// Kernel 2: fused attention, tf32 mma.sync (round-2 layout) +
//   - register prefetch of next tile's K/V and new Erel rows (hide GMEM lat)
//   - Erel 256-row ring buffer: stage only 64 new rows per k-tile
// ---------------------------------------------------------------------------
__global__ void __launch_bounds__(256, 1)
sa_attn_mma(const float* __restrict__ Erel)
{
    extern __shared__ float sm[];
    float* k_s = sm;                   // KT x PW
    float* v_s = k_s + KT * PW;        // KT x PW
    float* p_s = v_s + KT * PW;        // QT x PW  (softmax weights)
    float* b_s = p_s + QT * PW;        // QT x PW  (bias weights)
    float* e_s = b_s + QT * PW;        // 256 x PW (Erel ring)
    float* q_s = e_s;                  // alias: Q staging before main loop

    const int qt8 = blockIdx.x;
    const int h   = blockIdx.y;
    const int n   = blockIdx.z;
    const int q0  = qt8 * QT;
    const int rb0 = L_ - QT - q0;      // Erel band base row for kt=0 (>=0)
    const int kt_hasb_max = 2 * qt8 + 1;

    const size_t hb = ((size_t)(n * H_ + h)) * L_ * D_;
    const float* qp = g_q + hb;
    const float* kp = g_k + hb;
    const float* vp = g_v + hb;

    const int t    = threadIdx.x;
    const int lane = t & 31;
    const int w    = t >> 5;
    const int grp  = lane >> 2;    // 0..7
    const int qd   = lane & 3;     // 0..3
    const int wr0  = w * 16;       // warp's first local q row

    // ---- stage Q tile, build per-warp tf32 A fragments (held all kernel)
    for (int i = t; i < QT * 16; i += 256) {
        int row = i >> 4, cg = i & 15;
        float4 v4 = *(const float4*)&qp[(size_t)(q0 + row) * D_ + cg * 4];
        *(float4*)&q_s[row * PW + cg * 4] = v4;
    }
    __syncthreads();

    unsigned qa[8][4];
    {
        int rA = wr0 + grp, rB = rA + 8;
        #pragma unroll
        for (int ks = 0; ks < 8; ks++) {
            qa[ks][0] = f2tf(q_s[rA * PW + ks * 8 + qd]);
            qa[ks][1] = f2tf(q_s[rB * PW + ks * 8 + qd]);
            qa[ks][2] = f2tf(q_s[rA * PW + ks * 8 + qd + 4]);
            qa[ks][3] = f2tf(q_s[rB * PW + ks * 8 + qd + 4]);
        }
    }

    float accS[8][4] = {};
    float accB[8][4] = {};
    float m_lo = -INFINITY, m_hi = -INFINITY;
    float l_lo = 0.f, l_hi = 0.f;
    const float scale = 0.03125f;   // 1/sqrt(1024)

    const unsigned* vu = (const unsigned*)v_s;
    const unsigned* pu = (const unsigned*)p_s;
    const unsigned* bu = (const unsigned*)b_s;
    const unsigned* eu = (const unsigned*)e_s;

    const int prow = t >> 4;          // staging row this thread covers (+64 stride)
    const int pcg  = t & 15;          // staging column group

    // ---- prefetch tile 0 K/V into registers
    float4 kf[4], vf[4], ef[4];
    #pragma unroll
    for (int it = 0; it < 4; it++) {
        int row = prow + it * 16;
        kf[it] = *(const float4*)&kp[(size_t)row * D_ + pcg * 4];
        vf[it] = *(const float4*)&vp[(size_t)row * D_ + pcg * 4];
    }

    for (int kt = 0; kt < 16; kt++) {
        const int  k0   = kt * KT;
        const bool hasb = (kt <= kt_hasb_max);

        __syncthreads();   // previous tile's consumers done (also guards q_s alias)

        // ---- store prefetched K/V (tf32) ----
        #pragma unroll
        for (int it = 0; it < 4; it++) {
            int row = prow + it * 16;
            k_s[row * PW + pcg * 4 + 0] = f2tff(kf[it].x);
            k_s[row * PW + pcg * 4 + 1] = f2tff(kf[it].y);
            k_s[row * PW + pcg * 4 + 2] = f2tff(kf[it].z);
            k_s[row * PW + pcg * 4 + 3] = f2tff(kf[it].w);
            v_s[row * PW + pcg * 4 + 0] = f2tff(vf[it].x);
            v_s[row * PW + pcg * 4 + 1] = f2tff(vf[it].y);
            v_s[row * PW + pcg * 4 + 2] = f2tff(vf[it].z);
            v_s[row * PW + pcg * 4 + 3] = f2tff(vf[it].w);
        }

        // ---- Erel staging into 256-row ring ----
        if (kt == 0) {
            // first tile: stage full 192-row band into slots 0..191
            for (int i = t; i < 192 * 16; i += 256) {
                int row = i >> 4, cg = i & 15;
                int rr = rb0 + row;
                float4 e4 = (rr < L_) ? *(const float4*)&Erel[(size_t)rr * D_ + cg * 4]
                                      : make_float4(0.f, 0.f, 0.f, 0.f);
                e_s[row * PW + cg * 4 + 0] = f2tff(e4.x);
                e_s[row * PW + cg * 4 + 1] = f2tff(e4.y);
                e_s[row * PW + cg * 4 + 2] = f2tff(e4.z);
                e_s[row * PW + cg * 4 + 3] = f2tff(e4.w);
            }
        } else if (hasb) {
            // stage 64 new rows (prefetched) into slots ((kt*64 + 128) .. +191) mod 256
            const int sbase = ((kt & 3) * 64 + 128) & 255;
            #pragma unroll
            for (int it = 0; it < 4; it++) {
                int row = prow + it * 16;
                int slot = (sbase + row) & 255;
                e_s[slot * PW + pcg * 4 + 0] = f2tff(ef[it].x);
                e_s[slot * PW + pcg * 4 + 1] = f2tff(ef[it].y);
                e_s[slot * PW + pcg * 4 + 2] = f2tff(ef[it].z);
                e_s[slot * PW + pcg * 4 + 3] = f2tff(ef[it].w);
            }
        }

        // ---- prefetch next tile's K/V (+ new Erel rows) into registers ----
        if (kt < 15) {
            const int nk0 = (kt + 1) * KT;
            #pragma unroll
            for (int it = 0; it < 4; it++) {
                int row = nk0 + prow + it * 16;
                kf[it] = *(const float4*)&kp[(size_t)row * D_ + pcg * 4];
                vf[it] = *(const float4*)&vp[(size_t)row * D_ + pcg * 4];
            }
            if (kt + 1 <= kt_hasb_max) {
                const int rbn = rb0 + (kt + 1) * 64 + 128;   // new rows of next band
                #pragma unroll
                for (int it = 0; it < 4; it++) {
                    int rr = rbn + prow + it * 16;
                    ef[it] = (rr < L_) ? *(const float4*)&Erel[(size_t)rr * D_ + pcg * 4]
                                       : make_float4(0.f, 0.f, 0.f, 0.f);
                }
            }
        }
        __syncthreads();

        // ---- S = Q K^T (per warp: 16 x 64) ----
        float sfr[8][4];
        #pragma unroll
        for (int nt = 0; nt < 8; nt++) {
            sfr[nt][0] = sfr[nt][1] = sfr[nt][2] = sfr[nt][3] = 0.f;
            #pragma unroll
            for (int ks = 0; ks < 8; ks++) {
                unsigned b0 = __float_as_uint(k_s[(nt * 8 + grp) * PW + ks * 8 + qd]);
                unsigned b1 = __float_as_uint(k_s[(nt * 8 + grp) * PW + ks * 8 + qd + 4]);
                mma_tf32(sfr[nt], qa[ks][0], qa[ks][1], qa[ks][2], qa[ks][3], b0, b1);
            }
        }

        // ---- online softmax (rows lane>>2 and +8) ----
        float mt_lo = -INFINITY, mt_hi = -INFINITY;
        #pragma unroll
        for (int nt = 0; nt < 8; nt++) {
            #pragma unroll
            for (int r = 0; r < 4; r++) sfr[nt][r] *= scale;
            mt_lo = fmaxf(mt_lo, fmaxf(sfr[nt][0], sfr[nt][1]));
            mt_hi = fmaxf(mt_hi, fmaxf(sfr[nt][2], sfr[nt][3]));
        }
        mt_lo = fmaxf(mt_lo, __shfl_xor_sync(0xffffffffu, mt_lo, 1));
        mt_lo = fmaxf(mt_lo, __shfl_xor_sync(0xffffffffu, mt_lo, 2));
        mt_hi = fmaxf(mt_hi, __shfl_xor_sync(0xffffffffu, mt_hi, 1));
        mt_hi = fmaxf(mt_hi, __shfl_xor_sync(0xffffffffu, mt_hi, 2));

        float mn_lo = fmaxf(m_lo, mt_lo);
        float mn_hi = fmaxf(m_hi, mt_hi);
        float f_lo  = __expf(m_lo - mn_lo);
        float f_hi  = __expf(m_hi - mn_hi);
        m_lo = mn_lo; m_hi = mn_hi;

        float rs_lo = 0.f, rs_hi = 0.f;
        {
            int rA = wr0 + grp, rB = rA + 8;
            #pragma unroll
            for (int nt = 0; nt < 8; nt++) {
                float p0 = __expf(sfr[nt][0] - mn_lo);
                float p1 = __expf(sfr[nt][1] - mn_lo);
                float p2 = __expf(sfr[nt][2] - mn_hi);
                float p3 = __expf(sfr[nt][3] - mn_hi);
                rs_lo += p0 + p1;
                rs_hi += p2 + p3;
                float2 plo = make_float2(f2tff(p0), f2tff(p1));
                float2 phi = make_float2(f2tff(p2), f2tff(p3));
                *(float2*)&p_s[rA * PW + nt * 8 + 2 * qd] = plo;
                *(float2*)&p_s[rB * PW + nt * 8 + 2 * qd] = phi;
            }
        }
        rs_lo += __shfl_xor_sync(0xffffffffu, rs_lo, 1);
        rs_lo += __shfl_xor_sync(0xffffffffu, rs_lo, 2);
        rs_hi += __shfl_xor_sync(0xffffffffu, rs_hi, 1);
        rs_hi += __shfl_xor_sync(0xffffffffu, rs_hi, 2);
        l_lo = l_lo * f_lo + rs_lo;
        l_hi = l_hi * f_hi + rs_hi;
        #pragma unroll
        for (int nt = 0; nt < 8; nt++) {
            accS[nt][0] *= f_lo; accS[nt][1] *= f_lo;
            accS[nt][2] *= f_hi; accS[nt][3] *= f_hi;
        }

        // ---- bias scores: G = Q Eband^T (ring-indexed), scatter j = c-127+r.
        //      Per-thread windows tile every (r, j in [0,64)) exactly once. ----
        if (hasb) {
            const int nt_lo = (112 - wr0) >> 3;
            const int sb    = (kt & 3) * 64;     // ring slot base for this tile
            int rA = wr0 + grp, rB = rA + 8;
            #pragma unroll
            for (int nn = 0; nn < 10; nn++) {
                int nt = nt_lo + nn;
                int erow = (sb + nt * 8 + grp) & 255;
                float g[4] = {0.f, 0.f, 0.f, 0.f};
                #pragma unroll
                for (int ks = 0; ks < 8; ks++) {
                    unsigned b0 = eu[erow * PW + ks * 8 + qd];
                    unsigned b1 = eu[erow * PW + ks * 8 + qd + 4];
                    mma_tf32(g, qa[ks][0], qa[ks][1], qa[ks][2], qa[ks][3], b0, b1);
                }
                int cc = nt * 8 + 2 * qd;
                #pragma unroll
                for (int e = 0; e < 4; e++) {
                    int r = (e >= 2) ? rB : rA;
                    int c = cc + (e & 1);
                    int j = c - (QT - 1) + r;
                    if (j >= 0 && j < KT) {
                        bool ok = (k0 + j) <= (q0 + r);
                        b_s[r * PW + j] = ok ? f2tff(g[e]) : 0.f;
                    }
                }
            }
        }
        __syncwarp();   // p_s/b_s rows are warp-private; order STS -> LDS within warp

        // ---- accumulate P @ V (and B @ V) ----
        if (hasb) {
            int rA = wr0 + grp, rB = rA + 8;
            #pragma unroll
            for (int ks = 0; ks < 8; ks++) {
                unsigned pa0 = pu[rA * PW + ks * 8 + qd];
                unsigned pa1 = pu[rB * PW + ks * 8 + qd];
                unsigned pa2 = pu[rA * PW + ks * 8 + qd + 4];
                unsigned pa3 = pu[rB * PW + ks * 8 + qd + 4];
                unsigned ba0 = bu[rA * PW + ks * 8 + qd];
                unsigned ba1 = bu[rB * PW + ks * 8 + qd];
                unsigned ba2 = bu[rA * PW + ks * 8 + qd + 4];
                unsigned ba3 = bu[rB * PW + ks * 8 + qd + 4];
                #pragma unroll
                for (int nt = 0; nt < 8; nt++) {
                    unsigned vb0 = vu[(ks * 8 + qd) * PW + nt * 8 + grp];
                    unsigned vb1 = vu[(ks * 8 + qd + 4) * PW + nt * 8 + grp];
                    mma_tf32(accS[nt], pa0, pa1, pa2, pa3, vb0, vb1);
                    mma_tf32(accB[nt], ba0, ba1, ba2, ba3, vb0, vb1);
                }
            }
        } else {
            int rA = wr0 + grp, rB = rA + 8;
            #pragma unroll
            for (int ks = 0; ks < 8; ks++) {
                unsigned pa0 = pu[rA * PW + ks * 8 + qd];
                unsigned pa1 = pu[rB * PW + ks * 8 + qd];
                unsigned pa2 = pu[rA * PW + ks * 8 + qd + 4];
                unsigned pa3 = pu[rB * PW + ks * 8 + qd + 4];
                #pragma unroll
                for (int nt = 0; nt < 8; nt++) {
                    unsigned vb0 = vu[(ks * 8 + qd) * PW + nt * 8 + grp];
                    unsigned vb1 = vu[(ks * 8 + qd + 4) * PW + nt * 8 + grp];
                    mma_tf32(accS[nt], pa0, pa1, pa2, pa3, vb0, vb1);
                }
            }
        }
    }

    // ---- epilogue: out[n, q, h, d] = accS/l + accB ----
    {
        float inv_lo = 1.f / l_lo;
        float inv_hi = 1.f / l_hi;
        int iA = q0 + wr0 + grp;
        int iB = iA + 8;
        float* opA = g_attn + ((size_t)((n * L_ + iA) * H_ + h)) * D_;
        float* opB = g_attn + ((size_t)((n * L_ + iB) * H_ + h)) * D_;
        #pragma unroll
        for (int nt = 0; nt < 8; nt++) {
            int d = nt * 8 + 2 * qd;
            float2 olo = make_float2(accS[nt][0] * inv_lo + accB[nt][0],
                                     accS[nt][1] * inv_lo + accB[nt][1]);
            float2 ohi = make_float2(accS[nt][2] * inv_hi + accB[nt][2],
                                     accS[nt][3] * inv_hi + accB[nt][3]);
            *(float2*)&opA[d] = olo;
            *(float2*)&opB[d] = ohi;
        }
    }
}

// ---------------------------------------------------------------------------
// Kernel 3: output projection, tf32 mma.sync (round-2 version).
// out(8192,1024) = g_attn(8192,1024) @ Wo^T + bo
// ---------------------------------------------------------------------------
__global__ void __launch_bounds__(256, 1)
sa_outproj_mma(const float* __restrict__ Wo, const float* __restrict__ bo,
               float* __restrict__ out)
{
    extern __shared__ float sm[];
    float* a_s = sm;               // 128 x PW (tf32)
    float* w_s = sm + 128 * PW;    // 128 x PW (tf32)

    const int e0 = blockIdx.x * 128;
    const int m0 = blockIdx.y * 128;
    const int t    = threadIdx.x;
    const int lane = t & 31;
    const int w    = t >> 5;
    const int grp  = lane >> 2;
    const int qd   = lane & 3;
    const int wm   = (w >> 2) * 64;   // warp m offset (0 or 64)
    const int wn   = (w & 3) * 32;    // warp n offset (0,32,64,96)

    const unsigned* au = (const unsigned*)a_s;
    const unsigned* wu = (const unsigned*)w_s;

    float acc[4][4][4] = {};

    for (int kc = 0; kc < E_; kc += 64) {
        __syncthreads();
        for (int i = t; i < 128 * 16; i += 256) {
            int row = i >> 4, c = (i & 15) * 4;
            float4 a4 = *(const float4*)&g_attn[(size_t)(m0 + row) * E_ + kc + c];
            float4 w4 = *(const float4*)&Wo[(size_t)(e0 + row) * E_ + kc + c];
            a_s[row * PW + c + 0] = f2tff(a4.x);
            a_s[row * PW + c + 1] = f2tff(a4.y);
            a_s[row * PW + c + 2] = f2tff(a4.z);
            a_s[row * PW + c + 3] = f2tff(a4.w);
            w_s[row * PW + c + 0] = f2tff(w4.x);
            w_s[row * PW + c + 1] = f2tff(w4.y);
            w_s[row * PW + c + 2] = f2tff(w4.z);
            w_s[row * PW + c + 3] = f2tff(w4.w);
        }
        __syncthreads();

        #pragma unroll
        for (int ks = 0; ks < 8; ks++) {
            unsigned af[4][4];
            #pragma unroll
            for (int mt = 0; mt < 4; mt++) {
                int r = wm + mt * 16 + grp;
                af[mt][0] = au[r * PW + ks * 8 + qd];
                af[mt][1] = au[(r + 8) * PW + ks * 8 + qd];
                af[mt][2] = au[r * PW + ks * 8 + qd + 4];
                af[mt][3] = au[(r + 8) * PW + ks * 8 + qd + 4];
            }
            unsigned bf[4][2];
            #pragma unroll
            for (int nt = 0; nt < 4; nt++) {
                int nrow = wn + nt * 8 + grp;
                bf[nt][0] = wu[nrow * PW + ks * 8 + qd];
                bf[nt][1] = wu[nrow * PW + ks * 8 + qd + 4];
            }
            #pragma unroll
            for (int mt = 0; mt < 4; mt++)
                #pragma unroll
                for (int nt = 0; nt < 4; nt++)
                    mma_tf32(acc[mt][nt], af[mt][0], af[mt][1], af[mt][2], af[mt][3],
                             bf[nt][0], bf[nt][1]);
        }
    }

    // epilogue
    #pragma unroll
    for (int mt = 0; mt < 4; mt++) {
        int rA = m0 + wm + mt * 16 + grp;
        int rB = rA + 8;
        #pragma unroll
        for (int nt = 0; nt < 4; nt++) {
            int col = e0 + wn + nt * 8 + 2 * qd;
            float b0 = bo[col], b1 = bo[col + 1];
            float2 olo = make_float2(acc[mt][nt][0] + b0, acc[mt][nt][1] + b1);
            float2 ohi = make_float2(acc[mt][nt][2] + b0, acc[mt][nt][3] + b1);
            *(float2*)&out[(size_t)rA * E_ + col] = olo;
            *(float2*)&out[(size_t)rB * E_ + col] = ohi;
        }
    }
}

// ---------------------------------------------------------------------------
extern "C" void kernel_launch(void* const* d_in, const int* in_sizes, int n_in,
                              void* d_out, int out_size)
{
    const float* x    = (const float*)d_in[0];
    const float* Wq   = (const float*)d_in[1];
    const float* bq   = (const float*)d_in[2];
    const float* Wk   = (const float*)d_in[3];
    const float* bk   = (const float*)d_in[4];
    const float* Wv   = (const float*)d_in[5];
    const float* bv   = (const float*)d_in[6];
    const float* Erel = (const float*)d_in[7];
    const float* Wo   = (const float*)d_in[8];
    const float* bo   = (const float*)d_in[9];
    float* out = (float*)d_out;

    // attn: k(64) + v(64) + p(128) + b(128) + e_ring(256) rows, pitch PW
    const int attn_smem = (64 + 64 + 128 + 128 + 256) * PW * (int)sizeof(float); // 174,080 B
    const int proj_smem = 2 * 128 * PW * (int)sizeof(float);                     // 69,632 B
    cudaFuncSetAttribute(sa_attn_mma,
                         cudaFuncAttributeMaxDynamicSharedMemorySize, attn_smem);
    cudaFuncSetAttribute(sa_outproj_mma,
                         cudaFuncAttributeMaxDynamicSharedMemorySize, proj_smem);

    sa_qkv_kernel<<<(N_ * L_ * H_) / 64, 256>>>(x, Wq, bq, Wk, bk, Wv, bv);
    sa_attn_mma<<<dim3(L_ / QT, H_, N_), 256, attn_smem>>>(Erel);
    sa_outproj_mma<<<dim3(E_ / 128, (N_ * L_) / 128), 256, proj_smem>>>(Wo, bo, out);
}

// round 5
// speedup vs baseline: 2.0744x; 1.6661x over previous
#include <cuda_runtime.h>
#include <cuda_fp16.h>
#include <math.h>

#define N_ 8
#define L_ 1024
#define H_ 16
#define D_ 64
#define E_ 1024
#define PW 68    // fp32 smem pitch (qkv kernel)
#define PH 72    // fp16 smem pitch (144B = 9*16B rows: LDSM conflict-free)
#define QT 128
#define KT 64

// Scratch (static device globals: allocation-free per harness rules)
__device__ __half g_q[N_*H_*L_*D_];
__device__ __half g_k[N_*H_*L_*D_];
__device__ __half g_v[N_*H_*L_*D_];
__device__ __half g_attn[N_*L_*H_*D_];

// ---------------------------------------------------------------------------
// helpers
// ---------------------------------------------------------------------------
__device__ __forceinline__ unsigned sptr(const void* p) {
    return (unsigned)__cvta_generic_to_shared(p);
}
__device__ __forceinline__ void ldsm4(unsigned &r0, unsigned &r1, unsigned &r2, unsigned &r3,
                                      unsigned addr) {
    asm volatile("ldmatrix.sync.aligned.m8n8.x4.shared.b16 {%0,%1,%2,%3}, [%4];"
                 : "=r"(r0), "=r"(r1), "=r"(r2), "=r"(r3) : "r"(addr));
}
__device__ __forceinline__ void ldsm4t(unsigned &r0, unsigned &r1, unsigned &r2, unsigned &r3,
                                       unsigned addr) {
    asm volatile("ldmatrix.sync.aligned.m8n8.x4.trans.shared.b16 {%0,%1,%2,%3}, [%4];"
                 : "=r"(r0), "=r"(r1), "=r"(r2), "=r"(r3) : "r"(addr));
}
__device__ __forceinline__ void mma16(float c[4],
                                      unsigned a0, unsigned a1, unsigned a2, unsigned a3,
                                      unsigned b0, unsigned b1) {
    asm volatile(
        "mma.sync.aligned.m16n8k16.row.col.f32.f16.f16.f32 "
        "{%0,%1,%2,%3}, {%4,%5,%6,%7}, {%8,%9}, {%0,%1,%2,%3};"
        : "+f"(c[0]), "+f"(c[1]), "+f"(c[2]), "+f"(c[3])
        : "r"(a0), "r"(a1), "r"(a2), "r"(a3), "r"(b0), "r"(b1));
}

// ---------------------------------------------------------------------------
// Kernel 1: QKV projection (fp32 exact math, half outputs), 2 CTAs/SM.
// ---------------------------------------------------------------------------
__global__ void __launch_bounds__(256, 2)
sa_qkv_kernel(const float* __restrict__ x,
              const float* __restrict__ Wq, const float* __restrict__ bq,
              const float* __restrict__ Wk, const float* __restrict__ bk,
              const float* __restrict__ Wv, const float* __restrict__ bv)
{
    __shared__ float zs[64 * PW];
    __shared__ float ws[64 * PW];

    const int t  = threadIdx.x;
    const int tx = t & 15, ty = t >> 4;
    const int r0 = ty * 4;
    const int c0 = tx;
    const int R0 = blockIdx.x * 64;

    for (int i = t; i < 64 * 16; i += 256) {
        int row = i >> 4, cg = i & 15;
        float4 v4 = *(const float4*)&x[(size_t)(R0 + row) * D_ + cg * 4];
        *(float4*)&zs[row * PW + cg * 4] = v4;
    }

    size_t obase[4];
    #pragma unroll
    for (int r = 0; r < 4; r++) {
        int R = R0 + r0 + r;
        int n = R / (L_ * H_);
        int rem = R % (L_ * H_);
        int l = rem / H_;
        int h = rem % H_;
        obase[r] = ((size_t)((n * H_ + h) * L_ + l)) * D_;
    }

    const float* Ws[3] = {Wq, Wk, Wv};
    const float* Bs[3] = {bq, bk, bv};
    __half*      Gs[3] = {g_q, g_k, g_v};

    #pragma unroll
    for (int m = 0; m < 3; m++) {
        __syncthreads();
        for (int i = t; i < 64 * 16; i += 256) {
            int row = i >> 4, cg = i & 15;
            float4 v4 = *(const float4*)&Ws[m][row * D_ + cg * 4];
            *(float4*)&ws[row * PW + cg * 4] = v4;
        }
        __syncthreads();

        float acc[4][4] = {};
        #pragma unroll
        for (int d4 = 0; d4 < 16; d4++) {
            float4 zf[4], wf[4];
            #pragma unroll
            for (int r = 0; r < 4; r++) zf[r] = *(const float4*)&zs[(r0 + r) * PW + d4 * 4];
            #pragma unroll
            for (int c = 0; c < 4; c++) wf[c] = *(const float4*)&ws[(c0 + 16 * c) * PW + d4 * 4];
            #pragma unroll
            for (int r = 0; r < 4; r++)
                #pragma unroll
                for (int c = 0; c < 4; c++)
                    acc[r][c] += zf[r].x * wf[c].x + zf[r].y * wf[c].y
                               + zf[r].z * wf[c].z + zf[r].w * wf[c].w;
        }

        #pragma unroll
        for (int r = 0; r < 4; r++)
            #pragma unroll
            for (int c = 0; c < 4; c++)
                Gs[m][obase[r] + c0 + 16 * c] = __float2half_rn(acc[r][c] + Bs[m][c0 + 16 * c]);
    }
}

// ---------------------------------------------------------------------------
// Kernel 2: fused attention, fp16 m16n8k16 mma + ldmatrix.
// ---------------------------------------------------------------------------
__global__ void __launch_bounds__(256, 1)
sa_attn_mma(const float* __restrict__ Erel)
{
    extern __shared__ __half smh[];
    __half* k_s = smh;                 // 64 x PH
    __half* v_s = k_s + 64 * PH;       // 64 x PH
    __half* p_s = v_s + 64 * PH;       // 128 x PH
    __half* b_s = p_s + 128 * PH;      // 128 x PH
    __half* e_s = b_s + 128 * PH;      // 256 x PH (Erel ring)
    __half* q_s = e_s;                 // alias: Q staging before main loop

    const int qt8 = blockIdx.x;
    const int h   = blockIdx.y;
    const int n   = blockIdx.z;
    const int q0  = qt8 * QT;
    const int rb0 = L_ - QT - q0;
    const int kt_hasb_max = 2 * qt8 + 1;

    const size_t hb = ((size_t)(n * H_ + h)) * L_ * D_;
    const __half* qp = g_q + hb;
    const __half* kp = g_k + hb;
    const __half* vp = g_v + hb;

    const int t    = threadIdx.x;
    const int lane = t & 31;
    const int w    = t >> 5;
    const int grp  = lane >> 2;
    const int qd   = lane & 3;
    const int wr0  = w * 16;
    const int lg   = lane >> 3;     // ldmatrix lane group 0..3
    const int li   = lane & 7;      // ldmatrix row within group

    const unsigned kbase = sptr(k_s);
    const unsigned vbase = sptr(v_s);
    const unsigned pbase = sptr(p_s);
    const unsigned bbase = sptr(b_s);
    const unsigned ebase = sptr(e_s);

    // ---- stage Q tile (half, uint4 copies) ----
    #pragma unroll
    for (int p = 0; p < 4; p++) {
        int idx = t + p * 256;
        int row = idx >> 3, cg8 = idx & 7;
        uint4 u = ((const uint4*)(qp + (size_t)(q0 + row) * D_))[cg8];
        *(uint4*)(q_s + row * PH + cg8 * 8) = u;
    }
    __syncthreads();

    // Q a-frags (held in regs all kernel): qa[ks][0..3]
    unsigned qa[4][4];
    {
        unsigned qb = sptr(q_s);
        #pragma unroll
        for (int ks = 0; ks < 4; ks++) {
            unsigned addr = qb + ((wr0 + (lg & 1) * 8 + li) * PH + ks * 16 + (lg >> 1) * 8) * 2;
            ldsm4(qa[ks][0], qa[ks][1], qa[ks][2], qa[ks][3], addr);
        }
    }

    float accS[8][4] = {};
    float accB[8][4] = {};
    float m_lo = -INFINITY, m_hi = -INFINITY;
    float l_lo = 0.f, l_hi = 0.f;
    const float scale = 0.03125f;

    // K/V register prefetch (tile 0)
    uint4 kf[2], vf[2];
    #pragma unroll
    for (int p = 0; p < 2; p++) {
        int idx = t + p * 256;
        int row = idx >> 3, cg8 = idx & 7;
        kf[p] = ((const uint4*)(kp + (size_t)row * D_))[cg8];
        vf[p] = ((const uint4*)(vp + (size_t)row * D_))[cg8];
    }
    float4 ef[4];
    const int prow = t >> 4, pcg = t & 15;   // Erel staging mapping

    for (int kt = 0; kt < 16; kt++) {
        const int  k0   = kt * KT;
        const bool hasb = (kt <= kt_hasb_max);

        __syncthreads();   // previous tile's consumers done (also guards q_s alias)

        // ---- store prefetched K/V ----
        #pragma unroll
        for (int p = 0; p < 2; p++) {
            int idx = t + p * 256;
            int row = idx >> 3, cg8 = idx & 7;
            *(uint4*)(k_s + row * PH + cg8 * 8) = kf[p];
            *(uint4*)(v_s + row * PH + cg8 * 8) = vf[p];
        }

        // ---- Erel ring staging ----
        if (kt == 0) {
            for (int i = t; i < 192 * 16; i += 256) {
                int row = i >> 4, cg = i & 15;
                int rr = rb0 + row;
                float4 e4 = (rr < L_) ? *(const float4*)&Erel[(size_t)rr * D_ + cg * 4]
                                      : make_float4(0.f, 0.f, 0.f, 0.f);
                __half2 h01 = __floats2half2_rn(e4.x, e4.y);
                __half2 h23 = __floats2half2_rn(e4.z, e4.w);
                *(__half2*)(e_s + row * PH + cg * 4)     = h01;
                *(__half2*)(e_s + row * PH + cg * 4 + 2) = h23;
            }
        } else if (hasb) {
            const int sbase = ((kt & 3) * 64 + 128) & 255;
            #pragma unroll
            for (int it = 0; it < 4; it++) {
                int row = prow + it * 16;
                int slot = (sbase + row) & 255;
                __half2 h01 = __floats2half2_rn(ef[it].x, ef[it].y);
                __half2 h23 = __floats2half2_rn(ef[it].z, ef[it].w);
                *(__half2*)(e_s + slot * PH + pcg * 4)     = h01;
                *(__half2*)(e_s + slot * PH + pcg * 4 + 2) = h23;
            }
        }

        // ---- prefetch next tile ----
        if (kt < 15) {
            const int nk0 = (kt + 1) * KT;
            #pragma unroll
            for (int p = 0; p < 2; p++) {
                int idx = t + p * 256;
                int row = idx >> 3, cg8 = idx & 7;
                kf[p] = ((const uint4*)(kp + (size_t)(nk0 + row) * D_))[cg8];
                vf[p] = ((const uint4*)(vp + (size_t)(nk0 + row) * D_))[cg8];
            }
            if (kt + 1 <= kt_hasb_max) {
                const int rbn = rb0 + (kt + 1) * 64 + 128;
                #pragma unroll
                for (int it = 0; it < 4; it++) {
                    int rr = rbn + prow + it * 16;
                    ef[it] = (rr < L_) ? *(const float4*)&Erel[(size_t)rr * D_ + pcg * 4]
                                       : make_float4(0.f, 0.f, 0.f, 0.f);
                }
            }
        }
        __syncthreads();

        // ---- S = Q K^T ----
        float sfr[8][4];
        #pragma unroll
        for (int nt = 0; nt < 8; nt++)
            #pragma unroll
            for (int r = 0; r < 4; r++) sfr[nt][r] = 0.f;
        #pragma unroll
        for (int ntp = 0; ntp < 4; ntp++) {
            #pragma unroll
            for (int ks = 0; ks < 4; ks++) {
                unsigned r0, r1, r2, r3;
                unsigned addr = kbase + ((ntp * 16 + (lg & 1) * 8 + li) * PH
                                         + ks * 16 + (lg >> 1) * 8) * 2;
                ldsm4(r0, r1, r2, r3, addr);
                mma16(sfr[2*ntp],   qa[ks][0], qa[ks][1], qa[ks][2], qa[ks][3], r0, r2);
                mma16(sfr[2*ntp+1], qa[ks][0], qa[ks][1], qa[ks][2], qa[ks][3], r1, r3);
            }
        }

        // ---- online softmax ----
        float mt_lo = -INFINITY, mt_hi = -INFINITY;
        #pragma unroll
        for (int nt = 0; nt < 8; nt++) {
            #pragma unroll
            for (int r = 0; r < 4; r++) sfr[nt][r] *= scale;
            mt_lo = fmaxf(mt_lo, fmaxf(sfr[nt][0], sfr[nt][1]));
            mt_hi = fmaxf(mt_hi, fmaxf(sfr[nt][2], sfr[nt][3]));
        }
        mt_lo = fmaxf(mt_lo, __shfl_xor_sync(0xffffffffu, mt_lo, 1));
        mt_lo = fmaxf(mt_lo, __shfl_xor_sync(0xffffffffu, mt_lo, 2));
        mt_hi = fmaxf(mt_hi, __shfl_xor_sync(0xffffffffu, mt_hi, 1));
        mt_hi = fmaxf(mt_hi, __shfl_xor_sync(0xffffffffu, mt_hi, 2));

        float mn_lo = fmaxf(m_lo, mt_lo);
        float mn_hi = fmaxf(m_hi, mt_hi);
        float f_lo  = __expf(m_lo - mn_lo);
        float f_hi  = __expf(m_hi - mn_hi);
        m_lo = mn_lo; m_hi = mn_hi;

        const int rA = wr0 + grp, rB = rA + 8;
        float rs_lo = 0.f, rs_hi = 0.f;
        #pragma unroll
        for (int nt = 0; nt < 8; nt++) {
            float p0 = __expf(sfr[nt][0] - mn_lo);
            float p1 = __expf(sfr[nt][1] - mn_lo);
            float p2 = __expf(sfr[nt][2] - mn_hi);
            float p3 = __expf(sfr[nt][3] - mn_hi);
            rs_lo += p0 + p1;
            rs_hi += p2 + p3;
            *(__half2*)(p_s + rA * PH + nt * 8 + 2 * qd) = __floats2half2_rn(p0, p1);
            *(__half2*)(p_s + rB * PH + nt * 8 + 2 * qd) = __floats2half2_rn(p2, p3);
        }
        rs_lo += __shfl_xor_sync(0xffffffffu, rs_lo, 1);
        rs_lo += __shfl_xor_sync(0xffffffffu, rs_lo, 2);
        rs_hi += __shfl_xor_sync(0xffffffffu, rs_hi, 1);
        rs_hi += __shfl_xor_sync(0xffffffffu, rs_hi, 2);
        l_lo = l_lo * f_lo + rs_lo;
        l_hi = l_hi * f_hi + rs_hi;
        #pragma unroll
        for (int nt = 0; nt < 8; nt++) {
            accS[nt][0] *= f_lo; accS[nt][1] *= f_lo;
            accS[nt][2] *= f_hi; accS[nt][3] *= f_hi;
        }

        // ---- bias scores: G = Q Eband^T (ring), scatter j = c-127+r ----
        if (hasb) {
            const int nt_lo = (112 - wr0) >> 3;   // even
            const int sb    = (kt & 3) * 64;
            #pragma unroll
            for (int p5 = 0; p5 < 5; p5++) {
                int nt_e = nt_lo + 2 * p5;
                float ge[4] = {0.f, 0.f, 0.f, 0.f};
                float go[4] = {0.f, 0.f, 0.f, 0.f};
                int rowbase = ((sb + (nt_e + (lg & 1)) * 8) & 255) + li;
                #pragma unroll
                for (int ks = 0; ks < 4; ks++) {
                    unsigned r0, r1, r2, r3;
                    unsigned addr = ebase + (rowbase * PH + ks * 16 + (lg >> 1) * 8) * 2;
                    ldsm4(r0, r1, r2, r3, addr);
                    mma16(ge, qa[ks][0], qa[ks][1], qa[ks][2], qa[ks][3], r0, r2);
                    mma16(go, qa[ks][0], qa[ks][1], qa[ks][2], qa[ks][3], r1, r3);
                }
                #pragma unroll
                for (int half_i = 0; half_i < 2; half_i++) {
                    int nt = nt_e + half_i;
                    const float* g = half_i ? go : ge;
                    int cc = nt * 8 + 2 * qd;
                    #pragma unroll
                    for (int e = 0; e < 4; e++) {
                        int r = (e >= 2) ? rB : rA;
                        int c = cc + (e & 1);
                        int j = c - (QT - 1) + r;
                        if (j >= 0 && j < KT) {
                            bool ok = (k0 + j) <= (q0 + r);
                            b_s[r * PH + j] = ok ? __float2half_rn(g[e]) : __float2half_rn(0.f);
                        }
                    }
                }
            }
        }
        __syncwarp();   // p_s/b_s rows warp-private: order STS -> LDSM within warp

        // ---- accumulate P @ V (and B @ V) ----
        #pragma unroll
        for (int ks = 0; ks < 4; ks++) {
            unsigned pa0, pa1, pa2, pa3;
            unsigned addrP = pbase + ((wr0 + (lg & 1) * 8 + li) * PH
                                      + ks * 16 + (lg >> 1) * 8) * 2;
            ldsm4(pa0, pa1, pa2, pa3, addrP);
            unsigned ba0 = 0, ba1 = 0, ba2 = 0, ba3 = 0;
            if (hasb) {
                unsigned addrB = bbase + ((wr0 + (lg & 1) * 8 + li) * PH
                                          + ks * 16 + (lg >> 1) * 8) * 2;
                ldsm4(ba0, ba1, ba2, ba3, addrB);
            }
            #pragma unroll
            for (int ntp = 0; ntp < 4; ntp++) {
                unsigned v0, v1, v2, v3;
                unsigned addrV = vbase + ((ks * 16 + (lg & 1) * 8 + li) * PH
                                          + ntp * 16 + (lg >> 1) * 8) * 2;
                ldsm4t(v0, v1, v2, v3, addrV);
                mma16(accS[2*ntp],   pa0, pa1, pa2, pa3, v0, v1);
                mma16(accS[2*ntp+1], pa0, pa1, pa2, pa3, v2, v3);
                if (hasb) {
                    mma16(accB[2*ntp],   ba0, ba1, ba2, ba3, v0, v1);
                    mma16(accB[2*ntp+1], ba0, ba1, ba2, ba3, v2, v3);
                }
            }
        }
    }

    // ---- epilogue: g_attn[n, q, h, d] = accS/l + accB (half) ----
    {
        float inv_lo = 1.f / l_lo;
        float inv_hi = 1.f / l_hi;
        int iA = q0 + wr0 + grp;
        int iB = iA + 8;
        __half* opA = g_attn + ((size_t)((n * L_ + iA) * H_ + h)) * D_;
        __half* opB = g_attn + ((size_t)((n * L_ + iB) * H_ + h)) * D_;
        #pragma unroll
        for (int nt = 0; nt < 8; nt++) {
            int d = nt * 8 + 2 * qd;
            *(__half2*)(opA + d) = __floats2half2_rn(accS[nt][0] * inv_lo + accB[nt][0],
                                                     accS[nt][1] * inv_lo + accB[nt][1]);
            *(__half2*)(opB + d) = __floats2half2_rn(accS[nt][2] * inv_hi + accB[nt][2],
                                                     accS[nt][3] * inv_hi + accB[nt][3]);
        }
    }
}

// ---------------------------------------------------------------------------
// Kernel 3: output projection, fp16 m16n8k16 + ldmatrix.
// out(8192,1024) = g_attn(8192,1024) @ Wo^T + bo   (fp32 out)
// ---------------------------------------------------------------------------
__global__ void __launch_bounds__(256, 1)
sa_outproj_mma(const float* __restrict__ Wo, const float* __restrict__ bo,
               float* __restrict__ out)
{
    extern __shared__ __half smh[];
    __half* a_s = smh;                // 128 x PH
    __half* w_s = smh + 128 * PH;     // 128 x PH

    const int e0 = blockIdx.x * 128;
    const int m0 = blockIdx.y * 128;
    const int t    = threadIdx.x;
    const int lane = t & 31;
    const int w    = t >> 5;
    const int grp  = lane >> 2;
    const int qd   = lane & 3;
    const int wm   = (w >> 2) * 64;
    const int wn   = (w & 3) * 32;
    const int lg   = lane >> 3;
    const int li   = lane & 7;

    const unsigned abase = sptr(a_s);
    const unsigned wbase = sptr(w_s);

    float acc[4][4][4] = {};

    for (int kc = 0; kc < E_; kc += 64) {
        __syncthreads();
        // stage attn tile (half source, uint4 copy)
        #pragma unroll
        for (int p = 0; p < 4; p++) {
            int idx = t + p * 256;
            int row = idx >> 3, cg8 = idx & 7;
            uint4 u = ((const uint4*)(g_attn + (size_t)(m0 + row) * E_ + kc))[cg8];
            *(uint4*)(a_s + row * PH + cg8 * 8) = u;
        }
        // stage Wo tile (fp32 -> half)
        for (int i = t; i < 128 * 16; i += 256) {
            int row = i >> 4, cg = i & 15;
            float4 w4 = *(const float4*)&Wo[(size_t)(e0 + row) * E_ + kc + cg * 4];
            *(__half2*)(w_s + row * PH + cg * 4)     = __floats2half2_rn(w4.x, w4.y);
            *(__half2*)(w_s + row * PH + cg * 4 + 2) = __floats2half2_rn(w4.z, w4.w);
        }
        __syncthreads();

        #pragma unroll
        for (int ks = 0; ks < 4; ks++) {
            unsigned am[4][4];
            #pragma unroll
            for (int mt = 0; mt < 4; mt++) {
                unsigned addr = abase + ((wm + mt * 16 + (lg & 1) * 8 + li) * PH
                                         + ks * 16 + (lg >> 1) * 8) * 2;
                ldsm4(am[mt][0], am[mt][1], am[mt][2], am[mt][3], addr);
            }
            #pragma unroll
            for (int ntp = 0; ntp < 2; ntp++) {
                unsigned r0, r1, r2, r3;
                unsigned addr = wbase + ((wn + ntp * 16 + (lg & 1) * 8 + li) * PH
                                         + ks * 16 + (lg >> 1) * 8) * 2;
                ldsm4(r0, r1, r2, r3, addr);
                #pragma unroll
                for (int mt = 0; mt < 4; mt++) {
                    mma16(acc[mt][2*ntp],   am[mt][0], am[mt][1], am[mt][2], am[mt][3], r0, r2);
                    mma16(acc[mt][2*ntp+1], am[mt][0], am[mt][1], am[mt][2], am[mt][3], r1, r3);
                }
            }
        }
    }

    // epilogue (fp32 out)
    #pragma unroll
    for (int mt = 0; mt < 4; mt++) {
        int rA = m0 + wm + mt * 16 + grp;
        int rB = rA + 8;
        #pragma unroll
        for (int nt = 0; nt < 4; nt++) {
            int col = e0 + wn + nt * 8 + 2 * qd;
            float b0 = bo[col], b1 = bo[col + 1];
            float2 olo = make_float2(acc[mt][nt][0] + b0, acc[mt][nt][1] + b1);
            float2 ohi = make_float2(acc[mt][nt][2] + b0, acc[mt][nt][3] + b1);
            *(float2*)&out[(size_t)rA * E_ + col] = olo;
            *(float2*)&out[(size_t)rB * E_ + col] = ohi;
        }
    }
}

// ---------------------------------------------------------------------------
extern "C" void kernel_launch(void* const* d_in, const int* in_sizes, int n_in,
                              void* d_out, int out_size)
{
    const float* x    = (const float*)d_in[0];
    const float* Wq   = (const float*)d_in[1];
    const float* bq   = (const float*)d_in[2];
    const float* Wk   = (const float*)d_in[3];
    const float* bk   = (const float*)d_in[4];
    const float* Wv   = (const float*)d_in[5];
    const float* bv   = (const float*)d_in[6];
    const float* Erel = (const float*)d_in[7];
    const float* Wo   = (const float*)d_in[8];
    const float* bo   = (const float*)d_in[9];
    float* out = (float*)d_out;

    const int attn_smem = 640 * PH * (int)sizeof(__half);      // 92,160 B
    const int proj_smem = 2 * 128 * PH * (int)sizeof(__half);  // 36,864 B
    cudaFuncSetAttribute(sa_attn_mma,
                         cudaFuncAttributeMaxDynamicSharedMemorySize, attn_smem);
    cudaFuncSetAttribute(sa_outproj_mma,
                         cudaFuncAttributeMaxDynamicSharedMemorySize, proj_smem);

    sa_qkv_kernel<<<(N_ * L_ * H_) / 64, 256>>>(x, Wq, bq, Wk, bk, Wv, bv);
    sa_attn_mma<<<dim3(L_ / QT, H_, N_), 256, attn_smem>>>(Erel);
    sa_outproj_mma<<<dim3(E_ / 128, (N_ * L_) / 128), 256, proj_smem>>>(Wo, bo, out);
}

// round 6
// speedup vs baseline: 2.4375x; 1.1750x over previous
#include <cuda_runtime.h>
#include <cuda_fp16.h>
#include <math.h>

#define N_ 8
#define L_ 1024
#define H_ 16
#define D_ 64
#define E_ 1024
#define PH 72    // fp16 smem pitch (144B = 9*16B rows: LDSM + cp.async aligned, conflict-free)
#define QT 128
#define KT 64

// Scratch (static device globals: allocation-free per harness rules)
__device__ __half g_q[N_*H_*L_*D_];
__device__ __half g_k[N_*H_*L_*D_];
__device__ __half g_v[N_*H_*L_*D_];
__device__ __half g_attn[N_*L_*H_*D_];
__device__ __half g_wo[E_*E_];

// ---------------------------------------------------------------------------
// helpers
// ---------------------------------------------------------------------------
__device__ __forceinline__ unsigned sptr(const void* p) {
    return (unsigned)__cvta_generic_to_shared(p);
}
__device__ __forceinline__ void ldsm4(unsigned &r0, unsigned &r1, unsigned &r2, unsigned &r3,
                                      unsigned addr) {
    asm volatile("ldmatrix.sync.aligned.m8n8.x4.shared.b16 {%0,%1,%2,%3}, [%4];"
                 : "=r"(r0), "=r"(r1), "=r"(r2), "=r"(r3) : "r"(addr));
}
__device__ __forceinline__ void ldsm4t(unsigned &r0, unsigned &r1, unsigned &r2, unsigned &r3,
                                       unsigned addr) {
    asm volatile("ldmatrix.sync.aligned.m8n8.x4.trans.shared.b16 {%0,%1,%2,%3}, [%4];"
                 : "=r"(r0), "=r"(r1), "=r"(r2), "=r"(r3) : "r"(addr));
}
__device__ __forceinline__ void mma16(float c[4],
                                      unsigned a0, unsigned a1, unsigned a2, unsigned a3,
                                      unsigned b0, unsigned b1) {
    asm volatile(
        "mma.sync.aligned.m16n8k16.row.col.f32.f16.f16.f32 "
        "{%0,%1,%2,%3}, {%4,%5,%6,%7}, {%8,%9}, {%0,%1,%2,%3};"
        : "+f"(c[0]), "+f"(c[1]), "+f"(c[2]), "+f"(c[3])
        : "r"(a0), "r"(a1), "r"(a2), "r"(a3), "r"(b0), "r"(b1));
}
__device__ __forceinline__ void cp_async16(unsigned saddr, const void* g) {
    asm volatile("cp.async.cg.shared.global [%0], [%1], 16;" :: "r"(saddr), "l"(g));
}
__device__ __forceinline__ void cp_commit() {
    asm volatile("cp.async.commit_group;");
}
template<int NW> __device__ __forceinline__ void cp_wait() {
    asm volatile("cp.async.wait_group %0;" :: "n"(NW));
}

// ---------------------------------------------------------------------------
// Kernel 0: one-time Wo fp32 -> half conversion
// ---------------------------------------------------------------------------
__global__ void __launch_bounds__(256, 4)
sa_wo_convert(const float* __restrict__ Wo)
{
    int base = (blockIdx.x * 256 + threadIdx.x) * 4;
    float4 w4 = *(const float4*)&Wo[base];
    *(__half2*)(g_wo + base)     = __floats2half2_rn(w4.x, w4.y);
    *(__half2*)(g_wo + base + 2) = __floats2half2_rn(w4.z, w4.w);
}

// ---------------------------------------------------------------------------
// Kernel 1: QKV projection via fp16 mma with split-z:
//   q = (z_hi + z_lo) @ W_half^T + b,  z_hi = half(z), z_lo = half(z - z_hi)
// Only W's half-rounding contributes error (z split is exact to 2^-21).
// CTA: 128 rows x 64 cols, all three outputs. 8 warps of 16 rows.
// ---------------------------------------------------------------------------
__global__ void __launch_bounds__(256, 2)
sa_qkv_mma(const float* __restrict__ x,
           const float* __restrict__ Wq, const float* __restrict__ bq,
           const float* __restrict__ Wk, const float* __restrict__ bk,
           const float* __restrict__ Wv, const float* __restrict__ bv)
{
    extern __shared__ __half smh[];
    __half* zh_s = smh;                    // 128 x PH
    __half* zl_s = zh_s + 128 * PH;        // 128 x PH
    __half* w_s  = zl_s + 128 * PH;        // 3 x 64 x PH

    const int t    = threadIdx.x;
    const int lane = t & 31;
    const int w    = t >> 5;
    const int grp  = lane >> 2;
    const int qd   = lane & 3;
    const int wr0  = w * 16;
    const int lg   = lane >> 3;
    const int li   = lane & 7;
    const int R0   = blockIdx.x * 128;

    const float* Ws[3] = {Wq, Wk, Wv};
    const float* Bs[3] = {bq, bk, bv};
    __half*      Gs[3] = {g_q, g_k, g_v};

    // stage W (3 tiles of 64x64, fp32 -> half)
    for (int i = t; i < 3 * 64 * 16; i += 256) {
        int m = i >> 10, idx = i & 1023;
        int row = idx >> 4, cg = idx & 15;
        float4 w4 = *(const float4*)&Ws[m][row * D_ + cg * 4];
        __half* dst = w_s + m * 64 * PH + row * PH + cg * 4;
        *(__half2*)(dst)     = __floats2half2_rn(w4.x, w4.y);
        *(__half2*)(dst + 2) = __floats2half2_rn(w4.z, w4.w);
    }
    // stage z split (128x64 fp32 -> z_hi, z_lo halves)
    #pragma unroll
    for (int p = 0; p < 8; p++) {
        int idx = t + p * 256;
        int row = idx >> 4, cg = idx & 15;
        float4 v4 = *(const float4*)&x[(size_t)(R0 + row) * D_ + cg * 4];
        __half hx = __float2half_rn(v4.x), hy = __float2half_rn(v4.y);
        __half hz = __float2half_rn(v4.z), hw = __float2half_rn(v4.w);
        __half lx = __float2half_rn(v4.x - __half2float(hx));
        __half ly = __float2half_rn(v4.y - __half2float(hy));
        __half lz = __float2half_rn(v4.z - __half2float(hz));
        __half lw = __float2half_rn(v4.w - __half2float(hw));
        __half* dh = zh_s + row * PH + cg * 4;
        __half* dl = zl_s + row * PH + cg * 4;
        dh[0] = hx; dh[1] = hy; dh[2] = hz; dh[3] = hw;
        dl[0] = lx; dl[1] = ly; dl[2] = lz; dl[3] = lw;
    }
    __syncthreads();

    // A-frags for z_hi and z_lo (held in regs)
    unsigned ah[4][4], al[4][4];
    {
        unsigned bh = sptr(zh_s), bl = sptr(zl_s);
        #pragma unroll
        for (int ks = 0; ks < 4; ks++) {
            unsigned off = ((wr0 + (lg & 1) * 8 + li) * PH + ks * 16 + (lg >> 1) * 8) * 2;
            ldsm4(ah[ks][0], ah[ks][1], ah[ks][2], ah[ks][3], bh + off);
            ldsm4(al[ks][0], al[ks][1], al[ks][2], al[ks][3], bl + off);
        }
    }

    // output row mapping: R = (n*L + l)*H + h  ->  ((n*H+h)*L + l)*D
    size_t obA, obB;
    {
        int RA = R0 + wr0 + grp;
        int RB = RA + 8;
        int nA = RA >> 14, lA = (RA >> 4) & 1023, hA = RA & 15;
        int nB = RB >> 14, lB = (RB >> 4) & 1023, hB = RB & 15;
        obA = ((size_t)((nA * H_ + hA) * L_ + lA)) * D_;
        obB = ((size_t)((nB * H_ + hB) * L_ + lB)) * D_;
    }

    const unsigned wbase = sptr(w_s);
    #pragma unroll
    for (int m = 0; m < 3; m++) {
        float acc[8][4] = {};
        #pragma unroll
        for (int ks = 0; ks < 4; ks++) {
            #pragma unroll
            for (int ntp = 0; ntp < 4; ntp++) {
                unsigned r0, r1, r2, r3;
                unsigned addr = wbase + ((m * 64 + ntp * 16 + (lg & 1) * 8 + li) * PH
                                         + ks * 16 + (lg >> 1) * 8) * 2;
                ldsm4(r0, r1, r2, r3, addr);
                mma16(acc[2*ntp],   ah[ks][0], ah[ks][1], ah[ks][2], ah[ks][3], r0, r2);
                mma16(acc[2*ntp+1], ah[ks][0], ah[ks][1], ah[ks][2], ah[ks][3], r1, r3);
                mma16(acc[2*ntp],   al[ks][0], al[ks][1], al[ks][2], al[ks][3], r0, r2);
                mma16(acc[2*ntp+1], al[ks][0], al[ks][1], al[ks][2], al[ks][3], r1, r3);
            }
        }
        #pragma unroll
        for (int nt = 0; nt < 8; nt++) {
            int col = nt * 8 + 2 * qd;
            float b0 = Bs[m][col], b1 = Bs[m][col + 1];
            *(__half2*)(Gs[m] + obA + col) = __floats2half2_rn(acc[nt][0] + b0, acc[nt][1] + b1);
            *(__half2*)(Gs[m] + obB + col) = __floats2half2_rn(acc[nt][2] + b0, acc[nt][3] + b1);
        }
    }
}

// ---------------------------------------------------------------------------
// Kernel 2: fused attention, fp16 m16n8k16 mma + ldmatrix. (unchanged R5)
// ---------------------------------------------------------------------------
__global__ void __launch_bounds__(256, 1)
sa_attn_mma(const float* __restrict__ Erel)
{
    extern __shared__ __half smh[];
    __half* k_s = smh;                 // 64 x PH
    __half* v_s = k_s + 64 * PH;       // 64 x PH
    __half* p_s = v_s + 64 * PH;       // 128 x PH
    __half* b_s = p_s + 128 * PH;      // 128 x PH
    __half* e_s = b_s + 128 * PH;      // 256 x PH (Erel ring)
    __half* q_s = e_s;                 // alias: Q staging before main loop

    const int qt8 = blockIdx.x;
    const int h   = blockIdx.y;
    const int n   = blockIdx.z;
    const int q0  = qt8 * QT;
    const int rb0 = L_ - QT - q0;
    const int kt_hasb_max = 2 * qt8 + 1;

    const size_t hb = ((size_t)(n * H_ + h)) * L_ * D_;
    const __half* qp = g_q + hb;
    const __half* kp = g_k + hb;
    const __half* vp = g_v + hb;

    const int t    = threadIdx.x;
    const int lane = t & 31;
    const int w    = t >> 5;
    const int grp  = lane >> 2;
    const int qd   = lane & 3;
    const int wr0  = w * 16;
    const int lg   = lane >> 3;
    const int li   = lane & 7;

    const unsigned kbase = sptr(k_s);
    const unsigned vbase = sptr(v_s);
    const unsigned pbase = sptr(p_s);
    const unsigned bbase = sptr(b_s);
    const unsigned ebase = sptr(e_s);

    #pragma unroll
    for (int p = 0; p < 4; p++) {
        int idx = t + p * 256;
        int row = idx >> 3, cg8 = idx & 7;
        uint4 u = ((const uint4*)(qp + (size_t)(q0 + row) * D_))[cg8];
        *(uint4*)(q_s + row * PH + cg8 * 8) = u;
    }
    __syncthreads();

    unsigned qa[4][4];
    {
        unsigned qb = sptr(q_s);
        #pragma unroll
        for (int ks = 0; ks < 4; ks++) {
            unsigned addr = qb + ((wr0 + (lg & 1) * 8 + li) * PH + ks * 16 + (lg >> 1) * 8) * 2;
            ldsm4(qa[ks][0], qa[ks][1], qa[ks][2], qa[ks][3], addr);
        }
    }

    float accS[8][4] = {};
    float accB[8][4] = {};
    float m_lo = -INFINITY, m_hi = -INFINITY;
    float l_lo = 0.f, l_hi = 0.f;
    const float scale = 0.03125f;

    uint4 kf[2], vf[2];
    #pragma unroll
    for (int p = 0; p < 2; p++) {
        int idx = t + p * 256;
        int row = idx >> 3, cg8 = idx & 7;
        kf[p] = ((const uint4*)(kp + (size_t)row * D_))[cg8];
        vf[p] = ((const uint4*)(vp + (size_t)row * D_))[cg8];
    }
    float4 ef[4];
    const int prow = t >> 4, pcg = t & 15;

    for (int kt = 0; kt < 16; kt++) {
        const int  k0   = kt * KT;
        const bool hasb = (kt <= kt_hasb_max);

        __syncthreads();

        #pragma unroll
        for (int p = 0; p < 2; p++) {
            int idx = t + p * 256;
            int row = idx >> 3, cg8 = idx & 7;
            *(uint4*)(k_s + row * PH + cg8 * 8) = kf[p];
            *(uint4*)(v_s + row * PH + cg8 * 8) = vf[p];
        }

        if (kt == 0) {
            for (int i = t; i < 192 * 16; i += 256) {
                int row = i >> 4, cg = i & 15;
                int rr = rb0 + row;
                float4 e4 = (rr < L_) ? *(const float4*)&Erel[(size_t)rr * D_ + cg * 4]
                                      : make_float4(0.f, 0.f, 0.f, 0.f);
                *(__half2*)(e_s + row * PH + cg * 4)     = __floats2half2_rn(e4.x, e4.y);
                *(__half2*)(e_s + row * PH + cg * 4 + 2) = __floats2half2_rn(e4.z, e4.w);
            }
        } else if (hasb) {
            const int sbase = ((kt & 3) * 64 + 128) & 255;
            #pragma unroll
            for (int it = 0; it < 4; it++) {
                int row = prow + it * 16;
                int slot = (sbase + row) & 255;
                *(__half2*)(e_s + slot * PH + pcg * 4)     = __floats2half2_rn(ef[it].x, ef[it].y);
                *(__half2*)(e_s + slot * PH + pcg * 4 + 2) = __floats2half2_rn(ef[it].z, ef[it].w);
            }
        }

        if (kt < 15) {
            const int nk0 = (kt + 1) * KT;
            #pragma unroll
            for (int p = 0; p < 2; p++) {
                int idx = t + p * 256;
                int row = idx >> 3, cg8 = idx & 7;
                kf[p] = ((const uint4*)(kp + (size_t)(nk0 + row) * D_))[cg8];
                vf[p] = ((const uint4*)(vp + (size_t)(nk0 + row) * D_))[cg8];
            }
            if (kt + 1 <= kt_hasb_max) {
                const int rbn = rb0 + (kt + 1) * 64 + 128;
                #pragma unroll
                for (int it = 0; it < 4; it++) {
                    int rr = rbn + prow + it * 16;
                    ef[it] = (rr < L_) ? *(const float4*)&Erel[(size_t)rr * D_ + pcg * 4]
                                       : make_float4(0.f, 0.f, 0.f, 0.f);
                }
            }
        }
        __syncthreads();

        // ---- S = Q K^T ----
        float sfr[8][4];
        #pragma unroll
        for (int nt = 0; nt < 8; nt++)
            #pragma unroll
            for (int r = 0; r < 4; r++) sfr[nt][r] = 0.f;
        #pragma unroll
        for (int ntp = 0; ntp < 4; ntp++) {
            #pragma unroll
            for (int ks = 0; ks < 4; ks++) {
                unsigned r0, r1, r2, r3;
                unsigned addr = kbase + ((ntp * 16 + (lg & 1) * 8 + li) * PH
                                         + ks * 16 + (lg >> 1) * 8) * 2;
                ldsm4(r0, r1, r2, r3, addr);
                mma16(sfr[2*ntp],   qa[ks][0], qa[ks][1], qa[ks][2], qa[ks][3], r0, r2);
                mma16(sfr[2*ntp+1], qa[ks][0], qa[ks][1], qa[ks][2], qa[ks][3], r1, r3);
            }
        }

        // ---- online softmax ----
        float mt_lo = -INFINITY, mt_hi = -INFINITY;
        #pragma unroll
        for (int nt = 0; nt < 8; nt++) {
            #pragma unroll
            for (int r = 0; r < 4; r++) sfr[nt][r] *= scale;
            mt_lo = fmaxf(mt_lo, fmaxf(sfr[nt][0], sfr[nt][1]));
            mt_hi = fmaxf(mt_hi, fmaxf(sfr[nt][2], sfr[nt][3]));
        }
        mt_lo = fmaxf(mt_lo, __shfl_xor_sync(0xffffffffu, mt_lo, 1));
        mt_lo = fmaxf(mt_lo, __shfl_xor_sync(0xffffffffu, mt_lo, 2));
        mt_hi = fmaxf(mt_hi, __shfl_xor_sync(0xffffffffu, mt_hi, 1));
        mt_hi = fmaxf(mt_hi, __shfl_xor_sync(0xffffffffu, mt_hi, 2));

        float mn_lo = fmaxf(m_lo, mt_lo);
        float mn_hi = fmaxf(m_hi, mt_hi);
        float f_lo  = __expf(m_lo - mn_lo);
        float f_hi  = __expf(m_hi - mn_hi);
        m_lo = mn_lo; m_hi = mn_hi;

        const int rA = wr0 + grp, rB = rA + 8;
        float rs_lo = 0.f, rs_hi = 0.f;
        #pragma unroll
        for (int nt = 0; nt < 8; nt++) {
            float p0 = __expf(sfr[nt][0] - mn_lo);
            float p1 = __expf(sfr[nt][1] - mn_lo);
            float p2 = __expf(sfr[nt][2] - mn_hi);
            float p3 = __expf(sfr[nt][3] - mn_hi);
            rs_lo += p0 + p1;
            rs_hi += p2 + p3;
            *(__half2*)(p_s + rA * PH + nt * 8 + 2 * qd) = __floats2half2_rn(p0, p1);
            *(__half2*)(p_s + rB * PH + nt * 8 + 2 * qd) = __floats2half2_rn(p2, p3);
        }
        rs_lo += __shfl_xor_sync(0xffffffffu, rs_lo, 1);
        rs_lo += __shfl_xor_sync(0xffffffffu, rs_lo, 2);
        rs_hi += __shfl_xor_sync(0xffffffffu, rs_hi, 1);
        rs_hi += __shfl_xor_sync(0xffffffffu, rs_hi, 2);
        l_lo = l_lo * f_lo + rs_lo;
        l_hi = l_hi * f_hi + rs_hi;
        #pragma unroll
        for (int nt = 0; nt < 8; nt++) {
            accS[nt][0] *= f_lo; accS[nt][1] *= f_lo;
            accS[nt][2] *= f_hi; accS[nt][3] *= f_hi;
        }

        // ---- bias scores: G = Q Eband^T (ring), scatter j = c-127+r ----
        if (hasb) {
            const int nt_lo = (112 - wr0) >> 3;
            const int sb    = (kt & 3) * 64;
            #pragma unroll
            for (int p5 = 0; p5 < 5; p5++) {
                int nt_e = nt_lo + 2 * p5;
                float ge[4] = {0.f, 0.f, 0.f, 0.f};
                float go[4] = {0.f, 0.f, 0.f, 0.f};
                int rowbase = ((sb + (nt_e + (lg & 1)) * 8) & 255) + li;
                #pragma unroll
                for (int ks = 0; ks < 4; ks++) {
                    unsigned r0, r1, r2, r3;
                    unsigned addr = ebase + (rowbase * PH + ks * 16 + (lg >> 1) * 8) * 2;
                    ldsm4(r0, r1, r2, r3, addr);
                    mma16(ge, qa[ks][0], qa[ks][1], qa[ks][2], qa[ks][3], r0, r2);
                    mma16(go, qa[ks][0], qa[ks][1], qa[ks][2], qa[ks][3], r1, r3);
                }
                #pragma unroll
                for (int half_i = 0; half_i < 2; half_i++) {
                    int nt = nt_e + half_i;
                    const float* g = half_i ? go : ge;
                    int cc = nt * 8 + 2 * qd;
                    #pragma unroll
                    for (int e = 0; e < 4; e++) {
                        int r = (e >= 2) ? rB : rA;
                        int c = cc + (e & 1);
                        int j = c - (QT - 1) + r;
                        if (j >= 0 && j < KT) {
                            bool ok = (k0 + j) <= (q0 + r);
                            b_s[r * PH + j] = ok ? __float2half_rn(g[e]) : __float2half_rn(0.f);
                        }
                    }
                }
            }
        }
        __syncwarp();

        // ---- accumulate P @ V (and B @ V) ----
        #pragma unroll
        for (int ks = 0; ks < 4; ks++) {
            unsigned pa0, pa1, pa2, pa3;
            unsigned addrP = pbase + ((wr0 + (lg & 1) * 8 + li) * PH
                                      + ks * 16 + (lg >> 1) * 8) * 2;
            ldsm4(pa0, pa1, pa2, pa3, addrP);
            unsigned ba0 = 0, ba1 = 0, ba2 = 0, ba3 = 0;
            if (hasb) {
                unsigned addrB = bbase + ((wr0 + (lg & 1) * 8 + li) * PH
                                          + ks * 16 + (lg >> 1) * 8) * 2;
                ldsm4(ba0, ba1, ba2, ba3, addrB);
            }
            #pragma unroll
            for (int ntp = 0; ntp < 4; ntp++) {
                unsigned v0, v1, v2, v3;
                unsigned addrV = vbase + ((ks * 16 + (lg & 1) * 8 + li) * PH
                                          + ntp * 16 + (lg >> 1) * 8) * 2;
                ldsm4t(v0, v1, v2, v3, addrV);
                mma16(accS[2*ntp],   pa0, pa1, pa2, pa3, v0, v1);
                mma16(accS[2*ntp+1], pa0, pa1, pa2, pa3, v2, v3);
                if (hasb) {
                    mma16(accB[2*ntp],   ba0, ba1, ba2, ba3, v0, v1);
                    mma16(accB[2*ntp+1], ba0, ba1, ba2, ba3, v2, v3);
                }
            }
        }
    }

    // ---- epilogue ----
    {
        float inv_lo = 1.f / l_lo;
        float inv_hi = 1.f / l_hi;
        int iA = q0 + wr0 + grp;
        int iB = iA + 8;
        __half* opA = g_attn + ((size_t)((n * L_ + iA) * H_ + h)) * D_;
        __half* opB = g_attn + ((size_t)((n * L_ + iB) * H_ + h)) * D_;
        #pragma unroll
        for (int nt = 0; nt < 8; nt++) {
            int d = nt * 8 + 2 * qd;
            *(__half2*)(opA + d) = __floats2half2_rn(accS[nt][0] * inv_lo + accB[nt][0],
                                                     accS[nt][1] * inv_lo + accB[nt][1]);
            *(__half2*)(opB + d) = __floats2half2_rn(accS[nt][2] * inv_hi + accB[nt][2],
                                                     accS[nt][3] * inv_hi + accB[nt][3]);
        }
    }
}

// ---------------------------------------------------------------------------
// Kernel 3: output projection, fp16 mma + cp.async double-buffered pipeline.
// out(8192,1024) = g_attn(8192,1024) @ g_wo^T + bo   (fp32 out)
// ---------------------------------------------------------------------------
__global__ void __launch_bounds__(256, 1)
sa_outproj_mma(const float* __restrict__ bo, float* __restrict__ out)
{
    extern __shared__ __half smh[];
    __half* a0_s = smh;                   // 128 x PH
    __half* a1_s = a0_s + 128 * PH;
    __half* w0_s = a1_s + 128 * PH;
    __half* w1_s = w0_s + 128 * PH;

    const int e0 = blockIdx.x * 128;
    const int m0 = blockIdx.y * 128;
    const int t    = threadIdx.x;
    const int lane = t & 31;
    const int w    = t >> 5;
    const int grp  = lane >> 2;
    const int qd   = lane & 3;
    const int wm   = (w >> 2) * 64;
    const int wn   = (w & 3) * 32;
    const int lg   = lane >> 3;
    const int li   = lane & 7;

    const unsigned ab[2] = {sptr(a0_s), sptr(a1_s)};
    const unsigned wb[2] = {sptr(w0_s), sptr(w1_s)};

    float acc[4][4][4] = {};

    // issue cp.async group for chunk kc into buffer buf
    auto issue = [&](int buf, int kc) {
        #pragma unroll
        for (int p = 0; p < 4; p++) {
            int idx = t + p * 256;
            int row = idx >> 3, c8 = idx & 7;
            cp_async16(ab[buf] + (row * PH + c8 * 8) * 2,
                       g_attn + (size_t)(m0 + row) * E_ + kc + c8 * 8);
            cp_async16(wb[buf] + (row * PH + c8 * 8) * 2,
                       g_wo + (size_t)(e0 + row) * E_ + kc + c8 * 8);
        }
        cp_commit();
    };

    issue(0, 0);
    for (int c = 0; c < 16; c++) {
        if (c < 15) {
            issue((c + 1) & 1, (c + 1) * 64);
            cp_wait<1>();
        } else {
            cp_wait<0>();
        }
        __syncthreads();

        const unsigned abase = ab[c & 1];
        const unsigned wbase = wb[c & 1];
        #pragma unroll
        for (int ks = 0; ks < 4; ks++) {
            unsigned am[4][4];
            #pragma unroll
            for (int mt = 0; mt < 4; mt++) {
                unsigned addr = abase + ((wm + mt * 16 + (lg & 1) * 8 + li) * PH
                                         + ks * 16 + (lg >> 1) * 8) * 2;
                ldsm4(am[mt][0], am[mt][1], am[mt][2], am[mt][3], addr);
            }
            #pragma unroll
            for (int ntp = 0; ntp < 2; ntp++) {
                unsigned r0, r1, r2, r3;
                unsigned addr = wbase + ((wn + ntp * 16 + (lg & 1) * 8 + li) * PH
                                         + ks * 16 + (lg >> 1) * 8) * 2;
                ldsm4(r0, r1, r2, r3, addr);
                #pragma unroll
                for (int mt = 0; mt < 4; mt++) {
                    mma16(acc[mt][2*ntp],   am[mt][0], am[mt][1], am[mt][2], am[mt][3], r0, r2);
                    mma16(acc[mt][2*ntp+1], am[mt][0], am[mt][1], am[mt][2], am[mt][3], r1, r3);
                }
            }
        }
        __syncthreads();
    }

    #pragma unroll
    for (int mt = 0; mt < 4; mt++) {
        int rA = m0 + wm + mt * 16 + grp;
        int rB = rA + 8;
        #pragma unroll
        for (int nt = 0; nt < 4; nt++) {
            int col = e0 + wn + nt * 8 + 2 * qd;
            float b0 = bo[col], b1 = bo[col + 1];
            float2 olo = make_float2(acc[mt][nt][0] + b0, acc[mt][nt][1] + b1);
            float2 ohi = make_float2(acc[mt][nt][2] + b0, acc[mt][nt][3] + b1);
            *(float2*)&out[(size_t)rA * E_ + col] = olo;
            *(float2*)&out[(size_t)rB * E_ + col] = ohi;
        }
    }
}

// ---------------------------------------------------------------------------
extern "C" void kernel_launch(void* const* d_in, const int* in_sizes, int n_in,
                              void* d_out, int out_size)
{
    const float* x    = (const float*)d_in[0];
    const float* Wq   = (const float*)d_in[1];
    const float* bq   = (const float*)d_in[2];
    const float* Wk   = (const float*)d_in[3];
    const float* bk   = (const float*)d_in[4];
    const float* Wv   = (const float*)d_in[5];
    const float* bv   = (const float*)d_in[6];
    const float* Erel = (const float*)d_in[7];
    const float* Wo   = (const float*)d_in[8];
    const float* bo   = (const float*)d_in[9];
    float* out = (float*)d_out;

    const int qkv_smem  = (2 * 128 + 3 * 64) * PH * (int)sizeof(__half);  // 64,512 B
    const int attn_smem = 640 * PH * (int)sizeof(__half);                 // 92,160 B
    const int proj_smem = 4 * 128 * PH * (int)sizeof(__half);             // 73,728 B
    cudaFuncSetAttribute(sa_qkv_mma,
                         cudaFuncAttributeMaxDynamicSharedMemorySize, qkv_smem);
    cudaFuncSetAttribute(sa_attn_mma,
                         cudaFuncAttributeMaxDynamicSharedMemorySize, attn_smem);
    cudaFuncSetAttribute(sa_outproj_mma,
                         cudaFuncAttributeMaxDynamicSharedMemorySize, proj_smem);

    sa_wo_convert<<<E_ * E_ / 1024, 256>>>(Wo);
    sa_qkv_mma<<<(N_ * L_ * H_) / 128, 256, qkv_smem>>>(x, Wq, bq, Wk, bk, Wv, bv);
    sa_attn_mma<<<dim3(L_ / QT, H_, N_), 256, attn_smem>>>(Erel);
    sa_outproj_mma<<<dim3(E_ / 128, (N_ * L_) / 128), 256, proj_smem>>>(bo, out);
}

// round 7
// speedup vs baseline: 2.7951x; 1.1467x over previous
#include <cuda_runtime.h>
#include <cuda_fp16.h>
#include <math.h>

#define N_ 8
#define L_ 1024
#define H_ 16
#define D_ 64
#define E_ 1024
#define PH 72    // fp16 smem pitch (144B = 9*16B rows: LDSM + cp.async aligned, conflict-free)
#define QT 128
#define KT 64

// Scratch (static device globals: allocation-free per harness rules)
__device__ __half g_q[N_*H_*L_*D_];
__device__ __half g_k[N_*H_*L_*D_];
__device__ __half g_v[N_*H_*L_*D_];
__device__ __half g_attn[N_*L_*H_*D_];
__device__ __half g_wo[E_*E_];
__device__ __half g_erel[(L_+128)*D_];   // half Erel, padded with 128 zero rows

// ---------------------------------------------------------------------------
// helpers
// ---------------------------------------------------------------------------
__device__ __forceinline__ unsigned sptr(const void* p) {
    return (unsigned)__cvta_generic_to_shared(p);
}
__device__ __forceinline__ void ldsm4(unsigned &r0, unsigned &r1, unsigned &r2, unsigned &r3,
                                      unsigned addr) {
    asm volatile("ldmatrix.sync.aligned.m8n8.x4.shared.b16 {%0,%1,%2,%3}, [%4];"
                 : "=r"(r0), "=r"(r1), "=r"(r2), "=r"(r3) : "r"(addr));
}
__device__ __forceinline__ void ldsm4t(unsigned &r0, unsigned &r1, unsigned &r2, unsigned &r3,
                                       unsigned addr) {
    asm volatile("ldmatrix.sync.aligned.m8n8.x4.trans.shared.b16 {%0,%1,%2,%3}, [%4];"
                 : "=r"(r0), "=r"(r1), "=r"(r2), "=r"(r3) : "r"(addr));
}
__device__ __forceinline__ void mma16(float c[4],
                                      unsigned a0, unsigned a1, unsigned a2, unsigned a3,
                                      unsigned b0, unsigned b1) {
    asm volatile(
        "mma.sync.aligned.m16n8k16.row.col.f32.f16.f16.f32 "
        "{%0,%1,%2,%3}, {%4,%5,%6,%7}, {%8,%9}, {%0,%1,%2,%3};"
        : "+f"(c[0]), "+f"(c[1]), "+f"(c[2]), "+f"(c[3])
        : "r"(a0), "r"(a1), "r"(a2), "r"(a3), "r"(b0), "r"(b1));
}
__device__ __forceinline__ void cp_async16(unsigned saddr, const void* g) {
    asm volatile("cp.async.cg.shared.global [%0], [%1], 16;" :: "r"(saddr), "l"(g));
}
__device__ __forceinline__ void cp_commit() {
    asm volatile("cp.async.commit_group;");
}
template<int NW> __device__ __forceinline__ void cp_wait() {
    asm volatile("cp.async.wait_group %0;" :: "n"(NW));
}

// ---------------------------------------------------------------------------
// Kernel 0a: Wo fp32 -> half
// ---------------------------------------------------------------------------
__global__ void __launch_bounds__(256, 4)
sa_wo_convert(const float* __restrict__ Wo)
{
    int base = (blockIdx.x * 256 + threadIdx.x) * 4;
    float4 w4 = *(const float4*)&Wo[base];
    *(__half2*)(g_wo + base)     = __floats2half2_rn(w4.x, w4.y);
    *(__half2*)(g_wo + base + 2) = __floats2half2_rn(w4.z, w4.w);
}

// Kernel 0b: Erel fp32 -> half, rows >= L_ zeroed (pad for ring staging)
__global__ void __launch_bounds__(256, 4)
sa_erel_convert(const float* __restrict__ Erel)
{
    int base = (blockIdx.x * 256 + threadIdx.x) * 4;     // over (L_+128)*64
    if (base < L_ * D_) {
        float4 e4 = *(const float4*)&Erel[base];
        *(__half2*)(g_erel + base)     = __floats2half2_rn(e4.x, e4.y);
        *(__half2*)(g_erel + base + 2) = __floats2half2_rn(e4.z, e4.w);
    } else {
        *(__half2*)(g_erel + base)     = __floats2half2_rn(0.f, 0.f);
        *(__half2*)(g_erel + base + 2) = __floats2half2_rn(0.f, 0.f);
    }
}

// ---------------------------------------------------------------------------
// Kernel 1: QKV projection via fp16 mma with split-z (unchanged R6).
// ---------------------------------------------------------------------------
__global__ void __launch_bounds__(256, 2)
sa_qkv_mma(const float* __restrict__ x,
           const float* __restrict__ Wq, const float* __restrict__ bq,
           const float* __restrict__ Wk, const float* __restrict__ bk,
           const float* __restrict__ Wv, const float* __restrict__ bv)
{
    extern __shared__ __half smh[];
    __half* zh_s = smh;                    // 128 x PH
    __half* zl_s = zh_s + 128 * PH;        // 128 x PH
    __half* w_s  = zl_s + 128 * PH;        // 3 x 64 x PH

    const int t    = threadIdx.x;
    const int lane = t & 31;
    const int w    = t >> 5;
    const int grp  = lane >> 2;
    const int qd   = lane & 3;
    const int wr0  = w * 16;
    const int lg   = lane >> 3;
    const int li   = lane & 7;
    const int R0   = blockIdx.x * 128;

    const float* Ws[3] = {Wq, Wk, Wv};
    const float* Bs[3] = {bq, bk, bv};
    __half*      Gs[3] = {g_q, g_k, g_v};

    for (int i = t; i < 3 * 64 * 16; i += 256) {
        int m = i >> 10, idx = i & 1023;
        int row = idx >> 4, cg = idx & 15;
        float4 w4 = *(const float4*)&Ws[m][row * D_ + cg * 4];
        __half* dst = w_s + m * 64 * PH + row * PH + cg * 4;
        *(__half2*)(dst)     = __floats2half2_rn(w4.x, w4.y);
        *(__half2*)(dst + 2) = __floats2half2_rn(w4.z, w4.w);
    }
    #pragma unroll
    for (int p = 0; p < 8; p++) {
        int idx = t + p * 256;
        int row = idx >> 4, cg = idx & 15;
        float4 v4 = *(const float4*)&x[(size_t)(R0 + row) * D_ + cg * 4];
        __half hx = __float2half_rn(v4.x), hy = __float2half_rn(v4.y);
        __half hz = __float2half_rn(v4.z), hw = __float2half_rn(v4.w);
        __half lx = __float2half_rn(v4.x - __half2float(hx));
        __half ly = __float2half_rn(v4.y - __half2float(hy));
        __half lz = __float2half_rn(v4.z - __half2float(hz));
        __half lw = __float2half_rn(v4.w - __half2float(hw));
        __half* dh = zh_s + row * PH + cg * 4;
        __half* dl = zl_s + row * PH + cg * 4;
        dh[0] = hx; dh[1] = hy; dh[2] = hz; dh[3] = hw;
        dl[0] = lx; dl[1] = ly; dl[2] = lz; dl[3] = lw;
    }
    __syncthreads();

    unsigned ah[4][4], al[4][4];
    {
        unsigned bh = sptr(zh_s), bl = sptr(zl_s);
        #pragma unroll
        for (int ks = 0; ks < 4; ks++) {
            unsigned off = ((wr0 + (lg & 1) * 8 + li) * PH + ks * 16 + (lg >> 1) * 8) * 2;
            ldsm4(ah[ks][0], ah[ks][1], ah[ks][2], ah[ks][3], bh + off);
            ldsm4(al[ks][0], al[ks][1], al[ks][2], al[ks][3], bl + off);
        }
    }

    size_t obA, obB;
    {
        int RA = R0 + wr0 + grp;
        int RB = RA + 8;
        int nA = RA >> 14, lA = (RA >> 4) & 1023, hA = RA & 15;
        int nB = RB >> 14, lB = (RB >> 4) & 1023, hB = RB & 15;
        obA = ((size_t)((nA * H_ + hA) * L_ + lA)) * D_;
        obB = ((size_t)((nB * H_ + hB) * L_ + lB)) * D_;
    }

    const unsigned wbase = sptr(w_s);
    #pragma unroll
    for (int m = 0; m < 3; m++) {
        float acc[8][4] = {};
        #pragma unroll
        for (int ks = 0; ks < 4; ks++) {
            #pragma unroll
            for (int ntp = 0; ntp < 4; ntp++) {
                unsigned r0, r1, r2, r3;
                unsigned addr = wbase + ((m * 64 + ntp * 16 + (lg & 1) * 8 + li) * PH
                                         + ks * 16 + (lg >> 1) * 8) * 2;
                ldsm4(r0, r1, r2, r3, addr);
                mma16(acc[2*ntp],   ah[ks][0], ah[ks][1], ah[ks][2], ah[ks][3], r0, r2);
                mma16(acc[2*ntp+1], ah[ks][0], ah[ks][1], ah[ks][2], ah[ks][3], r1, r3);
                mma16(acc[2*ntp],   al[ks][0], al[ks][1], al[ks][2], al[ks][3], r0, r2);
                mma16(acc[2*ntp+1], al[ks][0], al[ks][1], al[ks][2], al[ks][3], r1, r3);
            }
        }
        #pragma unroll
        for (int nt = 0; nt < 8; nt++) {
            int col = nt * 8 + 2 * qd;
            float b0 = Bs[m][col], b1 = Bs[m][col + 1];
            *(__half2*)(Gs[m] + obA + col) = __floats2half2_rn(acc[nt][0] + b0, acc[nt][1] + b1);
            *(__half2*)(Gs[m] + obB + col) = __floats2half2_rn(acc[nt][2] + b0, acc[nt][3] + b1);
        }
    }
}

// ---------------------------------------------------------------------------
// Kernel 2: fused attention, fp16 mma + ldmatrix + cp.async staging, 2 CTA/SM.
// ---------------------------------------------------------------------------
__global__ void __launch_bounds__(256, 2)
sa_attn_mma()
{
    extern __shared__ __half smh[];
    __half* k0_s = smh;                  // 64 x PH
    __half* k1_s = k0_s + 64 * PH;       // 64 x PH
    __half* v0_s = k1_s + 64 * PH;       // 64 x PH
    __half* v1_s = v0_s + 64 * PH;       // 64 x PH
    __half* p_s  = v1_s + 64 * PH;       // 128 x PH
    __half* b_s  = p_s + 128 * PH;       // 128 x PH
    __half* e_s  = b_s + 128 * PH;       // 256 x PH (Erel ring)
    __half* q_s  = e_s;                  // alias: Q staging before main loop

    const int qt8 = blockIdx.x;
    const int h   = blockIdx.y;
    const int n   = blockIdx.z;
    const int q0  = qt8 * QT;
    const int rb0 = L_ - QT - q0;
    const int kt_hasb_max = 2 * qt8 + 1;

    const size_t hb = ((size_t)(n * H_ + h)) * L_ * D_;
    const __half* qp = g_q + hb;
    const __half* kp = g_k + hb;
    const __half* vp = g_v + hb;

    const int t    = threadIdx.x;
    const int lane = t & 31;
    const int w    = t >> 5;
    const int grp  = lane >> 2;
    const int qd   = lane & 3;
    const int wr0  = w * 16;
    const int lg   = lane >> 3;
    const int li   = lane & 7;

    const unsigned kb[2] = {sptr(k0_s), sptr(k1_s)};
    const unsigned vb[2] = {sptr(v0_s), sptr(v1_s)};
    const unsigned pbase = sptr(p_s);
    const unsigned bbase = sptr(b_s);
    const unsigned ebase = sptr(e_s);

    const int srow = t >> 3;      // cp.async staging row (stride 32)
    const int sc8  = t & 7;       // 16B chunk within row

    // ---- stage Q tile, build qa frags ----
    #pragma unroll
    for (int p = 0; p < 4; p++) {
        int idx = t + p * 256;
        int row = idx >> 3, cg8 = idx & 7;
        uint4 u = ((const uint4*)(qp + (size_t)(q0 + row) * D_))[cg8];
        *(uint4*)(q_s + row * PH + cg8 * 8) = u;
    }
    __syncthreads();

    unsigned qa[4][4];
    {
        unsigned qb = sptr(q_s);
        #pragma unroll
        for (int ks = 0; ks < 4; ks++) {
            unsigned addr = qb + ((wr0 + (lg & 1) * 8 + li) * PH + ks * 16 + (lg >> 1) * 8) * 2;
            ldsm4(qa[ks][0], qa[ks][1], qa[ks][2], qa[ks][3], addr);
        }
    }
    __syncthreads();   // all warps done reading q_s before e-ring cp.async overwrites it

    // ---- async staging lambdas ----
    auto issue_kv = [&](int buf, int kt_) {
        const __half* kg = kp + (size_t)kt_ * KT * D_;
        const __half* vg = vp + (size_t)kt_ * KT * D_;
        #pragma unroll
        for (int p = 0; p < 2; p++) {
            int row = srow + p * 32;
            cp_async16(kb[buf] + (row * PH + sc8 * 8) * 2, kg + row * D_ + sc8 * 8);
            cp_async16(vb[buf] + (row * PH + sc8 * 8) * 2, vg + row * D_ + sc8 * 8);
        }
    };
    auto issue_e_new = [&](int j) {   // 64 new band rows for tile j
        const int sbase = ((j & 3) * 64 + 128) & 255;
        const int rbn   = rb0 + j * 64 + 128;
        #pragma unroll
        for (int p = 0; p < 2; p++) {
            int row = srow + p * 32;
            cp_async16(ebase + (((sbase + row) & 255) * PH + sc8 * 8) * 2,
                       g_erel + (size_t)(rbn + row) * D_ + sc8 * 8);
        }
    };

    // prologue: tile 0 K/V + full 192-row Erel band (group 0)
    issue_kv(0, 0);
    #pragma unroll
    for (int p = 0; p < 6; p++) {
        int idx = t + p * 256;
        int row = idx >> 3, c8 = idx & 7;
        cp_async16(ebase + (row * PH + c8 * 8) * 2,
                   g_erel + (size_t)(rb0 + row) * D_ + c8 * 8);
    }
    cp_commit();

    float accS[8][4] = {};
    float accB[8][4] = {};
    float m_lo = -INFINITY, m_hi = -INFINITY;
    float l_lo = 0.f, l_hi = 0.f;
    const float scale = 0.03125f;

    for (int kt = 0; kt < 16; kt++) {
        const int  k0   = kt * KT;
        const bool hasb = (kt <= kt_hasb_max);

        if (kt < 15) {
            issue_kv((kt + 1) & 1, kt + 1);
            if (kt + 1 <= kt_hasb_max) issue_e_new(kt + 1);
            cp_commit();
            cp_wait<1>();
        } else {
            cp_wait<0>();
        }
        __syncthreads();

        const unsigned kbase = kb[kt & 1];
        const unsigned vbase = vb[kt & 1];

        // ---- S = Q K^T ----
        float sfr[8][4];
        #pragma unroll
        for (int nt = 0; nt < 8; nt++)
            #pragma unroll
            for (int r = 0; r < 4; r++) sfr[nt][r] = 0.f;
        #pragma unroll
        for (int ntp = 0; ntp < 4; ntp++) {
            #pragma unroll
            for (int ks = 0; ks < 4; ks++) {
                unsigned r0, r1, r2, r3;
                unsigned addr = kbase + ((ntp * 16 + (lg & 1) * 8 + li) * PH
                                         + ks * 16 + (lg >> 1) * 8) * 2;
                ldsm4(r0, r1, r2, r3, addr);
                mma16(sfr[2*ntp],   qa[ks][0], qa[ks][1], qa[ks][2], qa[ks][3], r0, r2);
                mma16(sfr[2*ntp+1], qa[ks][0], qa[ks][1], qa[ks][2], qa[ks][3], r1, r3);
            }
        }

        // ---- online softmax ----
        float mt_lo = -INFINITY, mt_hi = -INFINITY;
        #pragma unroll
        for (int nt = 0; nt < 8; nt++) {
            #pragma unroll
            for (int r = 0; r < 4; r++) sfr[nt][r] *= scale;
            mt_lo = fmaxf(mt_lo, fmaxf(sfr[nt][0], sfr[nt][1]));
            mt_hi = fmaxf(mt_hi, fmaxf(sfr[nt][2], sfr[nt][3]));
        }
        mt_lo = fmaxf(mt_lo, __shfl_xor_sync(0xffffffffu, mt_lo, 1));
        mt_lo = fmaxf(mt_lo, __shfl_xor_sync(0xffffffffu, mt_lo, 2));
        mt_hi = fmaxf(mt_hi, __shfl_xor_sync(0xffffffffu, mt_hi, 1));
        mt_hi = fmaxf(mt_hi, __shfl_xor_sync(0xffffffffu, mt_hi, 2));

        float mn_lo = fmaxf(m_lo, mt_lo);
        float mn_hi = fmaxf(m_hi, mt_hi);
        float f_lo  = __expf(m_lo - mn_lo);
        float f_hi  = __expf(m_hi - mn_hi);
        m_lo = mn_lo; m_hi = mn_hi;

        const int rA = wr0 + grp, rB = rA + 8;
        float rs_lo = 0.f, rs_hi = 0.f;
        #pragma unroll
        for (int nt = 0; nt < 8; nt++) {
            float p0 = __expf(sfr[nt][0] - mn_lo);
            float p1 = __expf(sfr[nt][1] - mn_lo);
            float p2 = __expf(sfr[nt][2] - mn_hi);
            float p3 = __expf(sfr[nt][3] - mn_hi);
            rs_lo += p0 + p1;
            rs_hi += p2 + p3;
            *(__half2*)(p_s + rA * PH + nt * 8 + 2 * qd) = __floats2half2_rn(p0, p1);
            *(__half2*)(p_s + rB * PH + nt * 8 + 2 * qd) = __floats2half2_rn(p2, p3);
        }
        rs_lo += __shfl_xor_sync(0xffffffffu, rs_lo, 1);
        rs_lo += __shfl_xor_sync(0xffffffffu, rs_lo, 2);
        rs_hi += __shfl_xor_sync(0xffffffffu, rs_hi, 1);
        rs_hi += __shfl_xor_sync(0xffffffffu, rs_hi, 2);
        l_lo = l_lo * f_lo + rs_lo;
        l_hi = l_hi * f_hi + rs_hi;
        #pragma unroll
        for (int nt = 0; nt < 8; nt++) {
            accS[nt][0] *= f_lo; accS[nt][1] *= f_lo;
            accS[nt][2] *= f_hi; accS[nt][3] *= f_hi;
        }

        // ---- bias scores: G = Q Eband^T (ring), scatter j = c-127+r ----
        if (hasb) {
            const int nt_lo = (112 - wr0) >> 3;
            const int sb    = (kt & 3) * 64;
            #pragma unroll
            for (int p5 = 0; p5 < 5; p5++) {
                int nt_e = nt_lo + 2 * p5;
                float ge[4] = {0.f, 0.f, 0.f, 0.f};
                float go[4] = {0.f, 0.f, 0.f, 0.f};
                int rowbase = ((sb + (nt_e + (lg & 1)) * 8) & 255) + li;
                #pragma unroll
                for (int ks = 0; ks < 4; ks++) {
                    unsigned r0, r1, r2, r3;
                    unsigned addr = ebase + (rowbase * PH + ks * 16 + (lg >> 1) * 8) * 2;
                    ldsm4(r0, r1, r2, r3, addr);
                    mma16(ge, qa[ks][0], qa[ks][1], qa[ks][2], qa[ks][3], r0, r2);
                    mma16(go, qa[ks][0], qa[ks][1], qa[ks][2], qa[ks][3], r1, r3);
                }
                #pragma unroll
                for (int half_i = 0; half_i < 2; half_i++) {
                    int nt = nt_e + half_i;
                    const float* g = half_i ? go : ge;
                    int cc = nt * 8 + 2 * qd;
                    #pragma unroll
                    for (int e = 0; e < 4; e++) {
                        int r = (e >= 2) ? rB : rA;
                        int c = cc + (e & 1);
                        int j = c - (QT - 1) + r;
                        if (j >= 0 && j < KT) {
                            bool ok = (k0 + j) <= (q0 + r);
                            b_s[r * PH + j] = ok ? __float2half_rn(g[e]) : __float2half_rn(0.f);
                        }
                    }
                }
            }
        }
        __syncwarp();   // p_s/b_s rows warp-private: order STS -> LDSM within warp

        // ---- accumulate P @ V (and B @ V) ----
        #pragma unroll
        for (int ks = 0; ks < 4; ks++) {
            unsigned pa0, pa1, pa2, pa3;
            unsigned addrP = pbase + ((wr0 + (lg & 1) * 8 + li) * PH
                                      + ks * 16 + (lg >> 1) * 8) * 2;
            ldsm4(pa0, pa1, pa2, pa3, addrP);
            unsigned ba0 = 0, ba1 = 0, ba2 = 0, ba3 = 0;
            if (hasb) {
                unsigned addrB = bbase + ((wr0 + (lg & 1) * 8 + li) * PH
                                          + ks * 16 + (lg >> 1) * 8) * 2;
                ldsm4(ba0, ba1, ba2, ba3, addrB);
            }
            #pragma unroll
            for (int ntp = 0; ntp < 4; ntp++) {
                unsigned v0, v1, v2, v3;
                unsigned addrV = vbase + ((ks * 16 + (lg & 1) * 8 + li) * PH
                                          + ntp * 16 + (lg >> 1) * 8) * 2;
                ldsm4t(v0, v1, v2, v3, addrV);
                mma16(accS[2*ntp],   pa0, pa1, pa2, pa3, v0, v1);
                mma16(accS[2*ntp+1], pa0, pa1, pa2, pa3, v2, v3);
                if (hasb) {
                    mma16(accB[2*ntp],   ba0, ba1, ba2, ba3, v0, v1);
                    mma16(accB[2*ntp+1], ba0, ba1, ba2, ba3, v2, v3);
                }
            }
        }
        __syncthreads();   // protect k/v buffer reuse by next iteration's cp.async
    }

    // ---- epilogue ----
    {
        float inv_lo = 1.f / l_lo;
        float inv_hi = 1.f / l_hi;
        int iA = q0 + wr0 + grp;
        int iB = iA + 8;
        __half* opA = g_attn + ((size_t)((n * L_ + iA) * H_ + h)) * D_;
        __half* opB = g_attn + ((size_t)((n * L_ + iB) * H_ + h)) * D_;
        #pragma unroll
        for (int nt = 0; nt < 8; nt++) {
            int d = nt * 8 + 2 * qd;
            *(__half2*)(opA + d) = __floats2half2_rn(accS[nt][0] * inv_lo + accB[nt][0],
                                                     accS[nt][1] * inv_lo + accB[nt][1]);
            *(__half2*)(opB + d) = __floats2half2_rn(accS[nt][2] * inv_hi + accB[nt][2],
                                                     accS[nt][3] * inv_hi + accB[nt][3]);
        }
    }
}

// ---------------------------------------------------------------------------
// Kernel 3: output projection, fp16 mma + cp.async double-buffer, 2 CTA/SM.
// ---------------------------------------------------------------------------
__global__ void __launch_bounds__(256, 2)
sa_outproj_mma(const float* __restrict__ bo, float* __restrict__ out)
{
    extern __shared__ __half smh[];
    __half* a0_s = smh;                   // 128 x PH
    __half* a1_s = a0_s + 128 * PH;
    __half* w0_s = a1_s + 128 * PH;
    __half* w1_s = w0_s + 128 * PH;

    const int e0 = blockIdx.x * 128;
    const int m0 = blockIdx.y * 128;
    const int t    = threadIdx.x;
    const int lane = t & 31;
    const int w    = t >> 5;
    const int grp  = lane >> 2;
    const int qd   = lane & 3;
    const int wm   = (w >> 2) * 64;
    const int wn   = (w & 3) * 32;
    const int lg   = lane >> 3;
    const int li   = lane & 7;

    const unsigned ab[2] = {sptr(a0_s), sptr(a1_s)};
    const unsigned wb[2] = {sptr(w0_s), sptr(w1_s)};

    float acc[4][4][4] = {};

    auto issue = [&](int buf, int kc) {
        #pragma unroll
        for (int p = 0; p < 4; p++) {
            int idx = t + p * 256;
            int row = idx >> 3, c8 = idx & 7;
            cp_async16(ab[buf] + (row * PH + c8 * 8) * 2,
                       g_attn + (size_t)(m0 + row) * E_ + kc + c8 * 8);
            cp_async16(wb[buf] + (row * PH + c8 * 8) * 2,
                       g_wo + (size_t)(e0 + row) * E_ + kc + c8 * 8);
        }
        cp_commit();
    };

    issue(0, 0);
    for (int c = 0; c < 16; c++) {
        if (c < 15) {
            issue((c + 1) & 1, (c + 1) * 64);
            cp_wait<1>();
        } else {
            cp_wait<0>();
        }
        __syncthreads();

        const unsigned abase = ab[c & 1];
        const unsigned wbase = wb[c & 1];
        #pragma unroll
        for (int ks = 0; ks < 4; ks++) {
            unsigned am[4][4];
            #pragma unroll
            for (int mt = 0; mt < 4; mt++) {
                unsigned addr = abase + ((wm + mt * 16 + (lg & 1) * 8 + li) * PH
                                         + ks * 16 + (lg >> 1) * 8) * 2;
                ldsm4(am[mt][0], am[mt][1], am[mt][2], am[mt][3], addr);
            }
            #pragma unroll
            for (int ntp = 0; ntp < 2; ntp++) {
                unsigned r0, r1, r2, r3;
                unsigned addr = wbase + ((wn + ntp * 16 + (lg & 1) * 8 + li) * PH
                                         + ks * 16 + (lg >> 1) * 8) * 2;
                ldsm4(r0, r1, r2, r3, addr);
                #pragma unroll
                for (int mt = 0; mt < 4; mt++) {
                    mma16(acc[mt][2*ntp],   am[mt][0], am[mt][1], am[mt][2], am[mt][3], r0, r2);
                    mma16(acc[mt][2*ntp+1], am[mt][0], am[mt][1], am[mt][2], am[mt][3], r1, r3);
                }
            }
        }
        __syncthreads();
    }

    #pragma unroll
    for (int mt = 0; mt < 4; mt++) {
        int rA = m0 + wm + mt * 16 + grp;
        int rB = rA + 8;
        #pragma unroll
        for (int nt = 0; nt < 4; nt++) {
            int col = e0 + wn + nt * 8 + 2 * qd;
            float b0 = bo[col], b1 = bo[col + 1];
            float2 olo = make_float2(acc[mt][nt][0] + b0, acc[mt][nt][1] + b1);
            float2 ohi = make_float2(acc[mt][nt][2] + b0, acc[mt][nt][3] + b1);
            *(float2*)&out[(size_t)rA * E_ + col] = olo;
            *(float2*)&out[(size_t)rB * E_ + col] = ohi;
        }
    }
}

// ---------------------------------------------------------------------------
extern "C" void kernel_launch(void* const* d_in, const int* in_sizes, int n_in,
                              void* d_out, int out_size)
{
    const float* x    = (const float*)d_in[0];
    const float* Wq   = (const float*)d_in[1];
    const float* bq   = (const float*)d_in[2];
    const float* Wk   = (const float*)d_in[3];
    const float* bk   = (const float*)d_in[4];
    const float* Wv   = (const float*)d_in[5];
    const float* bv   = (const float*)d_in[6];
    const float* Erel = (const float*)d_in[7];
    const float* Wo   = (const float*)d_in[8];
    const float* bo   = (const float*)d_in[9];
    float* out = (float*)d_out;

    const int qkv_smem  = (2 * 128 + 3 * 64) * PH * (int)sizeof(__half);  // 64,512 B
    const int attn_smem = 768 * PH * (int)sizeof(__half);                 // 110,592 B
    const int proj_smem = 4 * 128 * PH * (int)sizeof(__half);             // 73,728 B
    cudaFuncSetAttribute(sa_qkv_mma,
                         cudaFuncAttributeMaxDynamicSharedMemorySize, qkv_smem);
    cudaFuncSetAttribute(sa_attn_mma,
                         cudaFuncAttributeMaxDynamicSharedMemorySize, attn_smem);
    cudaFuncSetAttribute(sa_outproj_mma,
                         cudaFuncAttributeMaxDynamicSharedMemorySize, proj_smem);

    sa_wo_convert<<<E_ * E_ / 1024, 256>>>(Wo);
    sa_erel_convert<<<(L_ + 128) * D_ / 1024, 256>>>(Erel);
    sa_qkv_mma<<<(N_ * L_ * H_) / 128, 256, qkv_smem>>>(x, Wq, bq, Wk, bk, Wv, bv);
    sa_attn_mma<<<dim3(L_ / QT, H_, N_), 256, attn_smem>>>();
    sa_outproj_mma<<<dim3(E_ / 128, (N_ * L_) / 128), 256, proj_smem>>>(bo, out);
}